// round 2
// baseline (speedup 1.0000x reference)
#include <cuda_runtime.h>
#include <math.h>

// ---------------------------------------------------------------------------
// PatchNCE contrastive loss over 4 pyramid layers.
// Key identity: masked-diag logits multiset == full unmasked row multiset,
// so loss(b,s) = LSE_t(scores[b,s,t]/tau) - scores[b,s,s]/tau.
// ---------------------------------------------------------------------------

#define TAUF 0.07f

// Scratch (device globals; allocation in kernel_launch is forbidden).
__device__ float g_ft[8192 * 512];    // gathered diffs; reused as scores buffer
__device__ float g_hid[8192 * 512];   // hidden after relu
__device__ float g_z[8192 * 128];     // normalized output features
__device__ float g_partial[4 * 512];  // per-layer per-block LSE partial sums

__constant__ int c_DH[8] = {0, 0, 0, 1, 1, 2, 2, 2};
__constant__ int c_DW[8] = {0, 1, 2, 0, 2, 0, 1, 2};

// ---------------------------------------------------------------------------
// Gather: rows [0,4096) from fq, [4096,8192) from fk.
// out[n*C + ch] = feat[b, ch, h0+dh, w0+dw] - feat[b, ch, h0+1, w0+1]
// ---------------------------------------------------------------------------
__global__ void gather_kernel(const float* __restrict__ fq,
                              const float* __restrict__ fk,
                              const int* __restrict__ sid,
                              int C, int H, int W,
                              float* __restrict__ out)
{
    int idx = blockIdx.x * blockDim.x + threadIdx.x;
    int total = 8192 * C;
    if (idx >= total) return;
    int ch = idx % C;
    int n  = idx / C;
    const float* f = (n < 4096) ? fq : fk;
    int nl = n & 4095;
    int b = nl >> 9;
    int s = nl & 511;
    int sample = s >> 3;
    int nb = s & 7;
    int h0 = sid[sample * 2 + 0];
    int w0 = sid[sample * 2 + 1];
    int h = h0 + c_DH[nb];
    int w = w0 + c_DW[nb];
    const float* base = f + (size_t)(b * C + ch) * H * W;
    float v = base[h * W + w] - base[(h0 + 1) * W + (w0 + 1)];
    out[(size_t)n * C + ch] = v;
}

// ---------------------------------------------------------------------------
// SGEMM: C[m][n] = sum_k A[m][k] * B[n][k]  (+bias[n], optional relu)
// A: M x K row-major, B: N x K row-major ("NT" layout), C: M x N row-major.
// M multiple of 128; K multiple of 16; N guarded.
// BM=128, BN=64, BK=16, 256 threads, 8x4 thread tile.
// ---------------------------------------------------------------------------
#define BM 128
#define BN 64
#define BKK 16

__global__ void sgemm_kernel(const float* __restrict__ A,
                             const float* __restrict__ B,
                             const float* __restrict__ bias,
                             float* __restrict__ C,
                             int M, int N, int K, int relu,
                             long long strideA, long long strideB, long long strideC)
{
    A += (size_t)blockIdx.z * strideA;
    B += (size_t)blockIdx.z * strideB;
    C += (size_t)blockIdx.z * strideC;

    __shared__ __align__(16) float As[BKK][BM + 4];
    __shared__ __align__(16) float Bs[BKK][BN + 4];

    int tid = threadIdx.x;
    int m0 = blockIdx.y * BM;
    int n0 = blockIdx.x * BN;
    int tx = tid & 15;          // 0..15 -> 4 cols each
    int ty = tid >> 4;          // 0..15 -> 8 rows each

    float acc[8][4];
#pragma unroll
    for (int i = 0; i < 8; i++)
#pragma unroll
        for (int j = 0; j < 4; j++) acc[i][j] = 0.0f;

    for (int kt = 0; kt < K; kt += BKK) {
        // Load A tile: 128x16 = 512 float4, 2 per thread.
#pragma unroll
        for (int i = 0; i < 2; i++) {
            int t = tid + i * 256;
            int row = t >> 2;
            int k4 = t & 3;
            float4 v = *(const float4*)&A[(size_t)(m0 + row) * K + kt + k4 * 4];
            As[k4 * 4 + 0][row] = v.x;
            As[k4 * 4 + 1][row] = v.y;
            As[k4 * 4 + 2][row] = v.z;
            As[k4 * 4 + 3][row] = v.w;
        }
        // Load B tile: 64x16 = 256 float4, 1 per thread (guard N).
        {
            int row = tid >> 2;
            int k4 = tid & 3;
            float4 v = make_float4(0.f, 0.f, 0.f, 0.f);
            if (n0 + row < N)
                v = *(const float4*)&B[(size_t)(n0 + row) * K + kt + k4 * 4];
            Bs[k4 * 4 + 0][row] = v.x;
            Bs[k4 * 4 + 1][row] = v.y;
            Bs[k4 * 4 + 2][row] = v.z;
            Bs[k4 * 4 + 3][row] = v.w;
        }
        __syncthreads();

#pragma unroll
        for (int k = 0; k < BKK; k++) {
            float4 a0 = *(const float4*)&As[k][ty * 8];
            float4 a1 = *(const float4*)&As[k][ty * 8 + 4];
            float4 bb = *(const float4*)&Bs[k][tx * 4];
            float ar[8] = {a0.x, a0.y, a0.z, a0.w, a1.x, a1.y, a1.z, a1.w};
            float br[4] = {bb.x, bb.y, bb.z, bb.w};
#pragma unroll
            for (int i = 0; i < 8; i++)
#pragma unroll
                for (int j = 0; j < 4; j++)
                    acc[i][j] = fmaf(ar[i], br[j], acc[i][j]);
        }
        __syncthreads();
    }

#pragma unroll
    for (int i = 0; i < 8; i++) {
        int m = m0 + ty * 8 + i;
#pragma unroll
        for (int j = 0; j < 4; j++) {
            int n = n0 + tx * 4 + j;
            if (n < N) {
                float v = acc[i][j];
                if (bias) v += bias[n];
                if (relu) v = fmaxf(v, 0.0f);
                C[(size_t)m * N + n] = v;
            }
        }
    }
}

// ---------------------------------------------------------------------------
// Row L2-normalize in place: z[row] /= (||z[row]|| + 1e-7). One warp per row.
// ---------------------------------------------------------------------------
__global__ void norm_kernel(float* __restrict__ z, int N)
{
    int warp = (blockIdx.x * blockDim.x + threadIdx.x) >> 5;
    int lane = threadIdx.x & 31;
    if (warp >= 8192) return;
    float* row = z + (size_t)warp * N;
    float ss = 0.0f;
    for (int j = lane; j < N; j += 32) {
        float v = row[j];
        ss += v * v;
    }
#pragma unroll
    for (int o = 16; o; o >>= 1) ss += __shfl_xor_sync(0xffffffffu, ss, o);
    float inv = 1.0f / (sqrtf(ss) + 1e-7f);
    for (int j = lane; j < N; j += 32) row[j] *= inv;
}

// ---------------------------------------------------------------------------
// Per-row logsumexp minus diagonal. scores: [b][s][t] flattened, 4096 rows of
// 512. One warp per row; block (8 warps) writes one partial sum.
// ---------------------------------------------------------------------------
__global__ void lse_kernel(const float* __restrict__ scores,
                           float* __restrict__ partial, int layer)
{
    int row = blockIdx.x * 8 + (threadIdx.x >> 5);
    int lane = threadIdx.x & 31;
    int s = row & 511;
    const float* r = scores + (size_t)row * 512;

    float vals[16];
    float m = -1e30f;
#pragma unroll
    for (int i = 0; i < 16; i++) {
        vals[i] = r[lane + i * 32];
        m = fmaxf(m, vals[i]);
    }
#pragma unroll
    for (int o = 16; o; o >>= 1) m = fmaxf(m, __shfl_xor_sync(0xffffffffu, m, o));

    const float invtau = 1.0f / TAUF;
    float sum = 0.0f;
#pragma unroll
    for (int i = 0; i < 16; i++) sum += __expf((vals[i] - m) * invtau);
#pragma unroll
    for (int o = 16; o; o >>= 1) sum += __shfl_xor_sync(0xffffffffu, sum, o);

    float loss = 0.0f;
    if (lane == 0) {
        float diag = r[s];
        loss = (m - diag) * invtau + logf(sum);
    }

    __shared__ float sh[8];
    if (lane == 0) sh[threadIdx.x >> 5] = loss;
    __syncthreads();
    if (threadIdx.x == 0) {
        float t = 0.0f;
#pragma unroll
        for (int i = 0; i < 8; i++) t += sh[i];
        partial[layer * 512 + blockIdx.x] = t;
    }
}

// ---------------------------------------------------------------------------
// Final reduction: sum all partials, divide by 4096 (per-layer mean, summed).
// ---------------------------------------------------------------------------
__global__ void final_kernel(float* __restrict__ out)
{
    __shared__ float sh[256];
    float s = 0.0f;
    for (int i = threadIdx.x; i < 4 * 512; i += 256) s += g_partial[i];
    sh[threadIdx.x] = s;
    __syncthreads();
    for (int st = 128; st; st >>= 1) {
        if (threadIdx.x < st) sh[threadIdx.x] += sh[threadIdx.x + st];
        __syncthreads();
    }
    if (threadIdx.x == 0) out[0] = sh[0] / 4096.0f;
}

// ---------------------------------------------------------------------------
// Launch. Input ordering is detected at runtime:
//   Ordering A (signature): fq0..3, fk0..3, sid0..3, (w1,b1,w2,b2)x4, scalars
//   Ordering B (dict):      per-layer (fq, fk, sid, w1, b1, w2, b2), scalars
// Detection: in B, in_sizes[0]==in_sizes[1] (fq0,fk0 both 33.5M) and
// in_sizes[2]==128 (sid). In A, in_sizes[1]==16.7M (fq1).
// ---------------------------------------------------------------------------
extern "C" void kernel_launch(void* const* d_in, const int* in_sizes, int n_in,
                              void* d_out, int out_size)
{
    (void)n_in; (void)out_size;
    const int Cs[4] = {64, 128, 256, 512};
    const int Hs[4] = {256, 128, 64, 32};

    float *ft, *hid, *z, *partial;
    cudaGetSymbolAddress((void**)&ft, g_ft);
    cudaGetSymbolAddress((void**)&hid, g_hid);
    cudaGetSymbolAddress((void**)&z, g_z);
    cudaGetSymbolAddress((void**)&partial, g_partial);

    bool dict_order = (in_sizes[0] == in_sizes[1]) && (in_sizes[2] == 128);

    for (int l = 0; l < 4; l++) {
        int ifq, ifk, isid, iw1, ib1, iw2, ib2;
        if (dict_order) {
            int base = 7 * l;
            ifq = base; ifk = base + 1; isid = base + 2;
            iw1 = base + 3; ib1 = base + 4; iw2 = base + 5; ib2 = base + 6;
        } else {
            ifq = l; ifk = 4 + l; isid = 8 + l;
            iw1 = 12 + l * 4; ib1 = iw1 + 1; iw2 = iw1 + 2; ib2 = iw1 + 3;
        }
        const float* fq = (const float*)d_in[ifq];
        const float* fk = (const float*)d_in[ifk];
        const int* sid  = (const int*)d_in[isid];
        const float* w1 = (const float*)d_in[iw1];
        const float* b1 = (const float*)d_in[ib1];
        const float* w2 = (const float*)d_in[iw2];
        const float* b2 = (const float*)d_in[ib2];
        int C = Cs[l], H = Hs[l], W = Hs[l], Co = C / 4;

        // 1) Gather neighbor diffs (q rows 0..4095, k rows 4096..8191).
        int total = 8192 * C;
        gather_kernel<<<(total + 255) / 256, 256>>>(fq, fk, sid, C, H, W, ft);

        // 2) GEMM1: hid = relu(ft @ w1^T + b1)   [8192 x C]
        {
            dim3 grid((C + BN - 1) / BN, 8192 / BM, 1);
            sgemm_kernel<<<grid, 256>>>(ft, w1, b1, hid, 8192, C, C, 1, 0, 0, 0);
        }
        // 3) GEMM2: z = hid @ w2^T + b2          [8192 x Co]
        {
            dim3 grid((Co + BN - 1) / BN, 8192 / BM, 1);
            sgemm_kernel<<<grid, 256>>>(hid, w2, b2, z, 8192, Co, C, 0, 0, 0, 0);
        }
        // 4) Row L2 normalize in place.
        norm_kernel<<<8192 / 8, 256>>>(z, Co);

        // 5) Batched similarity: scores[b] = zq[b] @ zk[b]^T  [8 x 512 x 512]
        {
            dim3 grid(512 / BN, 512 / BM, 8);
            sgemm_kernel<<<grid, 256>>>(z, z + (size_t)4096 * Co, nullptr, ft,
                                        512, 512, Co, 0,
                                        (long long)512 * Co,
                                        (long long)512 * Co,
                                        (long long)512 * 512);
        }
        // 6) LSE - diag, per-block partial sums.
        lse_kernel<<<512, 256>>>(ft, partial, l);
    }

    final_kernel<<<1, 256>>>((float*)d_out);
}

// round 4
// speedup vs baseline: 1.2197x; 1.2197x over previous
#include <cuda_runtime.h>
#include <cuda_bf16.h>
#include <cstdint>
#include <math.h>

// ---------------------------------------------------------------------------
// PatchNCE contrastive loss over 4 pyramid layers.
// loss(b,s) = LSE_t(scores[b,s,t]/tau) - scores[b,s,s]/tau   (diag identity)
// All GEMMs run on tensor cores: bf16x3 split (hi+lo, 3 HMMA combos) with
// fp32 accumulation -> near-fp32 accuracy at tensor-core speed.
// ---------------------------------------------------------------------------

#define TAUF 0.07f

// Scratch (device globals; allocation in kernel_launch is forbidden).
__device__ __nv_bfloat16 g_fthi[8192 * 512];
__device__ __nv_bfloat16 g_ftlo[8192 * 512];
__device__ __nv_bfloat16 g_hidhi[8192 * 512];
__device__ __nv_bfloat16 g_hidlo[8192 * 512];
__device__ float         g_zf[8192 * 128];
__device__ __nv_bfloat16 g_zhi[8192 * 128];
__device__ __nv_bfloat16 g_zlo[8192 * 128];
__device__ float         g_scores[8 * 512 * 512];
__device__ __nv_bfloat16 g_whi[512 * 512 + 128 * 512];
__device__ __nv_bfloat16 g_wlo[512 * 512 + 128 * 512];
__device__ float         g_partial[4 * 512];

__constant__ int c_DH[8] = {0, 0, 0, 1, 1, 2, 2, 2};
__constant__ int c_DW[8] = {0, 1, 2, 0, 2, 0, 1, 2};

__device__ __forceinline__ void split_bf16(float x, __nv_bfloat16& h, __nv_bfloat16& l)
{
    h = __float2bfloat16(x);
    l = __float2bfloat16(x - __bfloat162float(h));
}

// ---------------------------------------------------------------------------
// Gather: rows [0,4096) from fq, [4096,8192) from fk. Writes split bf16.
// ---------------------------------------------------------------------------
__global__ void gather_kernel(const float* __restrict__ fq,
                              const float* __restrict__ fk,
                              const int* __restrict__ sid,
                              int C, int H, int W,
                              __nv_bfloat16* __restrict__ outhi,
                              __nv_bfloat16* __restrict__ outlo)
{
    int idx = blockIdx.x * blockDim.x + threadIdx.x;
    int total = 8192 * C;
    if (idx >= total) return;
    int ch = idx % C;
    int n  = idx / C;
    const float* f = (n < 4096) ? fq : fk;
    int nl = n & 4095;
    int b = nl >> 9;
    int s = nl & 511;
    int sample = s >> 3;
    int nb = s & 7;
    int h0 = sid[sample * 2 + 0];
    int w0 = sid[sample * 2 + 1];
    int h = h0 + c_DH[nb];
    int w = w0 + c_DW[nb];
    const float* base = f + (size_t)(b * C + ch) * H * W;
    float v = base[h * W + w] - base[(h0 + 1) * W + (w0 + 1)];
    __nv_bfloat16 hh, ll;
    split_bf16(v, hh, ll);
    outhi[(size_t)n * C + ch] = hh;
    outlo[(size_t)n * C + ch] = ll;
}

// ---------------------------------------------------------------------------
// Weight conversion: w1 (C*C) then w2 (C/4*C) concatenated into split arrays.
// ---------------------------------------------------------------------------
__global__ void wconv_kernel(const float* __restrict__ w1,
                             const float* __restrict__ w2,
                             int C,
                             __nv_bfloat16* __restrict__ whi,
                             __nv_bfloat16* __restrict__ wlo)
{
    int n1 = C * C;
    int total = n1 + (C / 4) * C;
    int idx = blockIdx.x * blockDim.x + threadIdx.x;
    if (idx >= total) return;
    float v = (idx < n1) ? w1[idx] : w2[idx - n1];
    __nv_bfloat16 hh, ll;
    split_bf16(v, hh, ll);
    whi[idx] = hh;
    wlo[idx] = ll;
}

// ---------------------------------------------------------------------------
// Tensor-core GEMM: C[m][n] = sum_k A[m][k]*B[n][k]  (A: MxK, B: NxK, NT)
// bf16x3: acc += Ahi*Bhi + Ahi*Blo + Alo*Bhi, fp32 accumulate.
// Block 128x64, BK=32, 8 warps (2 m x 4 n), warp tile 64x16.
// MODE 0: store fp32 C.   MODE 1: +bias, relu, split-store bf16 hi/lo.
// MODE 2: +bias, store fp32 C.
// M % 128 == 0, K % 16 == 0, N guarded.
// ---------------------------------------------------------------------------
__device__ __forceinline__ void ldsm4(uint32_t* r, uint32_t saddr)
{
    asm volatile("ldmatrix.sync.aligned.m8n8.x4.shared.b16 {%0,%1,%2,%3}, [%4];"
                 : "=r"(r[0]), "=r"(r[1]), "=r"(r[2]), "=r"(r[3])
                 : "r"(saddr));
}

__device__ __forceinline__ void mma16816(float* c, const uint32_t* a, const uint32_t* b)
{
    asm volatile(
        "mma.sync.aligned.m16n8k16.row.col.f32.bf16.bf16.f32 "
        "{%0,%1,%2,%3}, {%4,%5,%6,%7}, {%8,%9}, {%0,%1,%2,%3};"
        : "+f"(c[0]), "+f"(c[1]), "+f"(c[2]), "+f"(c[3])
        : "r"(a[0]), "r"(a[1]), "r"(a[2]), "r"(a[3]), "r"(b[0]), "r"(b[1]));
}

template <int MODE>
__global__ __launch_bounds__(256)
void mma_gemm(const __nv_bfloat16* __restrict__ Ahi, const __nv_bfloat16* __restrict__ Alo,
              const __nv_bfloat16* __restrict__ Bhi, const __nv_bfloat16* __restrict__ Blo,
              const float* __restrict__ bias,
              float* __restrict__ Cf,
              __nv_bfloat16* __restrict__ Chi, __nv_bfloat16* __restrict__ Clo,
              int M, int N, int K,
              long long sA, long long sB, long long sC)
{
    Ahi += (size_t)blockIdx.z * sA;
    Alo += (size_t)blockIdx.z * sA;
    Bhi += (size_t)blockIdx.z * sB;
    Blo += (size_t)blockIdx.z * sB;
    const size_t cOff = (size_t)blockIdx.z * sC;

    __shared__ __align__(16) __nv_bfloat16 As[2][128][40];
    __shared__ __align__(16) __nv_bfloat16 Bs[2][64][40];

    const int tid  = threadIdx.x;
    const int lane = tid & 31;
    const int wid  = tid >> 5;
    const int wm   = wid & 1;    // 2 warp rows of 64
    const int wn   = wid >> 1;   // 4 warp cols of 16
    const int m0   = blockIdx.y * 128;
    const int n0   = blockIdx.x * 64;

    float acc[4][2][4];
#pragma unroll
    for (int i = 0; i < 4; i++)
#pragma unroll
        for (int j = 0; j < 2; j++)
#pragma unroll
            for (int k = 0; k < 4; k++) acc[i][j][k] = 0.0f;

    const uint4 zero4 = make_uint4(0, 0, 0, 0);

    for (int kt = 0; kt < K; kt += 32) {
        // A tile: 128x32 halfs x2 arrays; 512 uint4 per array, 2 per thread.
#pragma unroll
        for (int i = 0; i < 2; i++) {
            int it  = tid + i * 256;
            int row = it >> 2;
            int cg  = (it & 3) << 3;
            uint4 vh = zero4, vl = zero4;
            if (kt + cg < K) {
                size_t off = (size_t)(m0 + row) * K + kt + cg;
                vh = *(const uint4*)(Ahi + off);
                vl = *(const uint4*)(Alo + off);
            }
            *(uint4*)&As[0][row][cg] = vh;
            *(uint4*)&As[1][row][cg] = vl;
        }
        // B tile: 64x32 halfs x2 arrays; 256 uint4, 1 per thread.
        {
            int row = tid >> 2;
            int cg  = (tid & 3) << 3;
            uint4 vh = zero4, vl = zero4;
            if (n0 + row < N && kt + cg < K) {
                size_t off = (size_t)(n0 + row) * K + kt + cg;
                vh = *(const uint4*)(Bhi + off);
                vl = *(const uint4*)(Blo + off);
            }
            *(uint4*)&Bs[0][row][cg] = vh;
            *(uint4*)&Bs[1][row][cg] = vl;
        }
        __syncthreads();

#pragma unroll
        for (int ks = 0; ks < 32; ks += 16) {
            uint32_t ah[4][4], al[4][4], bh[4], bl[4];
            int arow = wm * 64 + (lane & 15);
            int acol = ks + ((lane >> 4) << 3);
#pragma unroll
            for (int mi = 0; mi < 4; mi++) {
                ldsm4(ah[mi], (uint32_t)__cvta_generic_to_shared(&As[0][arow + mi * 16][acol]));
                ldsm4(al[mi], (uint32_t)__cvta_generic_to_shared(&As[1][arow + mi * 16][acol]));
            }
            int brow = wn * 16 + (lane & 7) + ((lane >> 4) << 3);
            int bcol = ks + (lane & 8);
            ldsm4(bh, (uint32_t)__cvta_generic_to_shared(&Bs[0][brow][bcol]));
            ldsm4(bl, (uint32_t)__cvta_generic_to_shared(&Bs[1][brow][bcol]));
#pragma unroll
            for (int mi = 0; mi < 4; mi++)
#pragma unroll
                for (int ni = 0; ni < 2; ni++) {
                    mma16816(acc[mi][ni], ah[mi], &bh[ni * 2]);
                    mma16816(acc[mi][ni], ah[mi], &bl[ni * 2]);
                    mma16816(acc[mi][ni], al[mi], &bh[ni * 2]);
                }
        }
        __syncthreads();
    }

    // Epilogue. Fragment: c0,c1 -> (row=g, col=tg,tg+1); c2,c3 -> row g+8.
    const int g  = lane >> 2;
    const int tg = (lane & 3) << 1;
#pragma unroll
    for (int mi = 0; mi < 4; mi++)
#pragma unroll
        for (int ni = 0; ni < 2; ni++) {
            int col = n0 + wn * 16 + ni * 8 + tg;
            if (col >= N) continue;
#pragma unroll
            for (int hf = 0; hf < 2; hf++) {
                int row = m0 + wm * 64 + mi * 16 + g + hf * 8;
                float v0 = acc[mi][ni][hf * 2 + 0];
                float v1 = acc[mi][ni][hf * 2 + 1];
                if (MODE == 0) {
                    Cf[cOff + (size_t)row * N + col]     = v0;
                    Cf[cOff + (size_t)row * N + col + 1] = v1;
                } else {
                    v0 += bias[col];
                    v1 += bias[col + 1];
                    if (MODE == 1) {
                        v0 = fmaxf(v0, 0.0f);
                        v1 = fmaxf(v1, 0.0f);
                        __nv_bfloat16 h0, l0, h1, l1;
                        split_bf16(v0, h0, l0);
                        split_bf16(v1, h1, l1);
                        size_t o = (size_t)row * N + col;
                        Chi[o] = h0; Chi[o + 1] = h1;
                        Clo[o] = l0; Clo[o + 1] = l1;
                    } else {
                        Cf[(size_t)row * N + col]     = v0;
                        Cf[(size_t)row * N + col + 1] = v1;
                    }
                }
            }
        }
}

// ---------------------------------------------------------------------------
// Row L2-normalize: read fp32 z, write split bf16. One warp per row.
// ---------------------------------------------------------------------------
__global__ void norm_kernel(const float* __restrict__ z,
                            __nv_bfloat16* __restrict__ zhi,
                            __nv_bfloat16* __restrict__ zlo, int N)
{
    int warp = (blockIdx.x * blockDim.x + threadIdx.x) >> 5;
    int lane = threadIdx.x & 31;
    if (warp >= 8192) return;
    const float* row = z + (size_t)warp * N;
    float ss = 0.0f;
    for (int j = lane; j < N; j += 32) {
        float v = row[j];
        ss += v * v;
    }
#pragma unroll
    for (int o = 16; o; o >>= 1) ss += __shfl_xor_sync(0xffffffffu, ss, o);
    float inv = 1.0f / (sqrtf(ss) + 1e-7f);
    for (int j = lane; j < N; j += 32) {
        float v = row[j] * inv;
        __nv_bfloat16 h, l;
        split_bf16(v, h, l);
        zhi[(size_t)warp * N + j] = h;
        zlo[(size_t)warp * N + j] = l;
    }
}

// ---------------------------------------------------------------------------
// Per-row logsumexp minus diagonal. 4096 rows of 512; one warp per row.
// ---------------------------------------------------------------------------
__global__ void lse_kernel(const float* __restrict__ scores,
                           float* __restrict__ partial, int layer)
{
    int row = blockIdx.x * 8 + (threadIdx.x >> 5);
    int lane = threadIdx.x & 31;
    int s = row & 511;
    const float* r = scores + (size_t)row * 512;

    float vals[16];
    float m = -1e30f;
#pragma unroll
    for (int i = 0; i < 16; i++) {
        vals[i] = r[lane + i * 32];
        m = fmaxf(m, vals[i]);
    }
#pragma unroll
    for (int o = 16; o; o >>= 1) m = fmaxf(m, __shfl_xor_sync(0xffffffffu, m, o));

    const float invtau = 1.0f / TAUF;
    float sum = 0.0f;
#pragma unroll
    for (int i = 0; i < 16; i++) sum += __expf((vals[i] - m) * invtau);
#pragma unroll
    for (int o = 16; o; o >>= 1) sum += __shfl_xor_sync(0xffffffffu, sum, o);

    float loss = 0.0f;
    if (lane == 0) {
        float diag = r[s];
        loss = (m - diag) * invtau + logf(sum);
    }

    __shared__ float sh[8];
    if (lane == 0) sh[threadIdx.x >> 5] = loss;
    __syncthreads();
    if (threadIdx.x == 0) {
        float t = 0.0f;
#pragma unroll
        for (int i = 0; i < 8; i++) t += sh[i];
        partial[layer * 512 + blockIdx.x] = t;
    }
}

__global__ void final_kernel(float* __restrict__ out)
{
    __shared__ float sh[256];
    float s = 0.0f;
    for (int i = threadIdx.x; i < 4 * 512; i += 256) s += g_partial[i];
    sh[threadIdx.x] = s;
    __syncthreads();
    for (int st = 128; st; st >>= 1) {
        if (threadIdx.x < st) sh[threadIdx.x] += sh[threadIdx.x + st];
        __syncthreads();
    }
    if (threadIdx.x == 0) out[0] = sh[0] / 4096.0f;
}

// ---------------------------------------------------------------------------
extern "C" void kernel_launch(void* const* d_in, const int* in_sizes, int n_in,
                              void* d_out, int out_size)
{
    (void)n_in; (void)out_size;
    const int Cs[4] = {64, 128, 256, 512};
    const int Hs[4] = {256, 128, 64, 32};

    __nv_bfloat16 *fthi, *ftlo, *hidhi, *hidlo, *zhi, *zlo, *whi, *wlo;
    float *zf, *scores, *partial;
    cudaGetSymbolAddress((void**)&fthi, g_fthi);
    cudaGetSymbolAddress((void**)&ftlo, g_ftlo);
    cudaGetSymbolAddress((void**)&hidhi, g_hidhi);
    cudaGetSymbolAddress((void**)&hidlo, g_hidlo);
    cudaGetSymbolAddress((void**)&zf, g_zf);
    cudaGetSymbolAddress((void**)&zhi, g_zhi);
    cudaGetSymbolAddress((void**)&zlo, g_zlo);
    cudaGetSymbolAddress((void**)&scores, g_scores);
    cudaGetSymbolAddress((void**)&whi, g_whi);
    cudaGetSymbolAddress((void**)&wlo, g_wlo);
    cudaGetSymbolAddress((void**)&partial, g_partial);

    bool dict_order = (in_sizes[0] == in_sizes[1]) && (in_sizes[2] == 128);

    for (int l = 0; l < 4; l++) {
        int ifq, ifk, isid, iw1, ib1, iw2, ib2;
        if (dict_order) {
            int base = 7 * l;
            ifq = base; ifk = base + 1; isid = base + 2;
            iw1 = base + 3; ib1 = base + 4; iw2 = base + 5; ib2 = base + 6;
        } else {
            ifq = l; ifk = 4 + l; isid = 8 + l;
            iw1 = 12 + l * 4; ib1 = iw1 + 1; iw2 = iw1 + 2; ib2 = iw1 + 3;
        }
        const float* fq = (const float*)d_in[ifq];
        const float* fk = (const float*)d_in[ifk];
        const int* sid  = (const int*)d_in[isid];
        const float* w1 = (const float*)d_in[iw1];
        const float* b1 = (const float*)d_in[ib1];
        const float* w2 = (const float*)d_in[iw2];
        const float* b2 = (const float*)d_in[ib2];
        int C = Cs[l], H = Hs[l], W = Hs[l], Co = C / 4;

        // 1) Gather neighbor diffs -> split bf16.
        int total = 8192 * C;
        gather_kernel<<<(total + 255) / 256, 256>>>(fq, fk, sid, C, H, W, fthi, ftlo);

        // 1b) Weight conversion (w1 at 0, w2 at C*C).
        int wtotal = C * C + Co * C;
        wconv_kernel<<<(wtotal + 255) / 256, 256>>>(w1, w2, C, whi, wlo);

        // 2) GEMM1: hid = relu(ft @ w1^T + b1) -> split bf16.
        {
            dim3 grid((C + 63) / 64, 8192 / 128, 1);
            mma_gemm<1><<<grid, 256>>>(fthi, ftlo, whi, wlo, b1,
                                       nullptr, hidhi, hidlo,
                                       8192, C, C, 0, 0, 0);
        }
        // 3) GEMM2: zf = hid @ w2^T + b2 (fp32).
        {
            dim3 grid((Co + 63) / 64, 8192 / 128, 1);
            mma_gemm<2><<<grid, 256>>>(hidhi, hidlo, whi + (size_t)C * C, wlo + (size_t)C * C,
                                       b2, zf, nullptr, nullptr,
                                       8192, Co, C, 0, 0, 0);
        }
        // 4) Row L2 normalize -> split bf16.
        norm_kernel<<<8192 / 8, 256>>>(zf, zhi, zlo, Co);

        // 5) Batched similarity: scores[b] = zq[b] @ zk[b]^T  [8 x 512 x 512]
        {
            dim3 grid(512 / 64, 512 / 128, 8);
            mma_gemm<0><<<grid, 256>>>(zhi, zlo,
                                       zhi + (size_t)4096 * Co, zlo + (size_t)4096 * Co,
                                       nullptr, scores, nullptr, nullptr,
                                       512, 512, Co,
                                       (long long)512 * Co, (long long)512 * Co,
                                       (long long)512 * 512);
        }
        // 6) LSE - diag, per-block partial sums.
        lse_kernel<<<512, 256>>>(scores, partial, l);
    }

    final_kernel<<<1, 256>>>((float*)d_out);
}

// round 5
// speedup vs baseline: 1.6099x; 1.3200x over previous
#include <cuda_runtime.h>
#include <cuda_bf16.h>
#include <cstdint>
#include <math.h>

// ---------------------------------------------------------------------------
// PatchNCE contrastive loss, 4 pyramid layers, stage-batched:
// every pipeline stage is ONE kernel launch covering all 4 layers
// (blockIdx-range decode), so the 148-SM chip is filled instead of running
// 26 under-occupied launches. GEMMs: bf16x3 split on HMMA, fp32 accum.
// loss(b,s) = LSE_t(scores[b,s,t]/tau) - scores[b,s,s]/tau  (diag identity)
// ---------------------------------------------------------------------------

#define TAUF 0.07f

// Layer constants: C = 64<<l, H = W = 256>>l, Co = C/4 = 16<<l.
// cumC[l]  = sum of previous C   (per-row offsets into ft/hid arrays)
// cumZ[l]  = sum of previous Co  (offsets into z arrays)
// cumW[l]  = sum of previous (C*C + C*C/4) weight elements
__constant__ int c_cumC[4] = {0, 64, 192, 448};
__constant__ int c_cumZ[4] = {0, 16, 48, 112};
__constant__ int c_cumW[4] = {0, 5120, 25600, 107520};

__constant__ int c_DH[8] = {0, 0, 0, 1, 1, 2, 2, 2};
__constant__ int c_DW[8] = {0, 1, 2, 0, 2, 0, 1, 2};

// Scratch (device globals; allocation in kernel_launch is forbidden).
__device__ __nv_bfloat16 g_fthi[8192 * 960];
__device__ __nv_bfloat16 g_ftlo[8192 * 960];
__device__ __nv_bfloat16 g_hidhi[8192 * 960];
__device__ __nv_bfloat16 g_hidlo[8192 * 960];
__device__ float         g_zf[8192 * 240];
__device__ __nv_bfloat16 g_zhi[8192 * 240];
__device__ __nv_bfloat16 g_zlo[8192 * 240];
__device__ float         g_scores[4 * 8 * 512 * 512];
__device__ __nv_bfloat16 g_whi[435200];
__device__ __nv_bfloat16 g_wlo[435200];
__device__ float         g_partial[4 * 512];

struct InPtrs {
    const float* fq[4];
    const float* fk[4];
    const int*   sid[4];
    const float* w1[4];
    const float* b1[4];
    const float* w2[4];
    const float* b2[4];
};

__device__ __forceinline__ void split_bf16(float x, __nv_bfloat16& h, __nv_bfloat16& l)
{
    h = __float2bfloat16(x);
    l = __float2bfloat16(x - __bfloat162float(h));
}

// ---------------------------------------------------------------------------
// Gather all layers. Blocks per layer = 8192*C/256 = 32*C:
// 2048, 4096, 8192, 16384 -> cum 2048, 6144, 14336, 30720.
// ---------------------------------------------------------------------------
__global__ void gather_all(InPtrs ip)
{
    int b = blockIdx.x;
    int l = (b < 2048) ? 0 : (b < 6144) ? 1 : (b < 14336) ? 2 : 3;
    const int gbase[4] = {0, 2048, 6144, 14336};
    int C = 64 << l, H = 256 >> l, W = H;
    int idx = (b - gbase[l]) * 256 + threadIdx.x;   // < 8192*C (exact multiple)

    int ch = idx % C;
    int n  = idx / C;
    const float* f = (n < 4096) ? ip.fq[l] : ip.fk[l];
    int nl = n & 4095;
    int bb = nl >> 9;
    int s  = nl & 511;
    int sample = s >> 3;
    int nb = s & 7;
    const int* sid = ip.sid[l];
    int h0 = sid[sample * 2 + 0];
    int w0 = sid[sample * 2 + 1];
    int h = h0 + c_DH[nb];
    int w = w0 + c_DW[nb];
    const float* base = f + (size_t)(bb * C + ch) * H * W;
    float v = base[h * W + w] - base[(h0 + 1) * W + (w0 + 1)];
    __nv_bfloat16 hh, ll;
    split_bf16(v, hh, ll);
    size_t off = (size_t)8192 * c_cumC[l] + (size_t)n * C + ch;
    g_fthi[off] = hh;
    g_ftlo[off] = ll;
}

// ---------------------------------------------------------------------------
// Weight conversion, all layers. Elements per layer = 1.25*C*C; blocks:
// 20, 80, 320, 1280 -> cum 20, 100, 420, 1700.
// ---------------------------------------------------------------------------
__global__ void wconv_all(InPtrs ip)
{
    int b = blockIdx.x;
    int l = (b < 20) ? 0 : (b < 100) ? 1 : (b < 420) ? 2 : 3;
    const int wb[4] = {0, 20, 100, 420};
    int C = 64 << l;
    int n1 = C * C;
    int idx = (b - wb[l]) * 256 + threadIdx.x;      // < 1.25*C*C (exact multiple)
    float v = (idx < n1) ? ip.w1[l][idx] : ip.w2[l][idx - n1];
    __nv_bfloat16 hh, ll;
    split_bf16(v, hh, ll);
    g_whi[c_cumW[l] + idx] = hh;
    g_wlo[c_cumW[l] + idx] = ll;
}

// ---------------------------------------------------------------------------
// Tensor-core GEMM tile: C[m][n] = sum_k A[m][k]*B[n][k]  (NT)
// bf16x3: acc += Ahi*Bhi + Ahi*Blo + Alo*Bhi, fp32 accumulate.
// Tile 128x64, BK=32, 8 warps (2m x 4n), warp tile 64x16.
// MODE 0: store fp32. MODE 1: +bias, relu, split bf16. MODE 2: +bias, fp32.
// ---------------------------------------------------------------------------
__device__ __forceinline__ void ldsm4(uint32_t* r, uint32_t saddr)
{
    asm volatile("ldmatrix.sync.aligned.m8n8.x4.shared.b16 {%0,%1,%2,%3}, [%4];"
                 : "=r"(r[0]), "=r"(r[1]), "=r"(r[2]), "=r"(r[3])
                 : "r"(saddr));
}

__device__ __forceinline__ void mma16816(float* c, const uint32_t* a, const uint32_t* b)
{
    asm volatile(
        "mma.sync.aligned.m16n8k16.row.col.f32.bf16.bf16.f32 "
        "{%0,%1,%2,%3}, {%4,%5,%6,%7}, {%8,%9}, {%0,%1,%2,%3};"
        : "+f"(c[0]), "+f"(c[1]), "+f"(c[2]), "+f"(c[3])
        : "r"(a[0]), "r"(a[1]), "r"(a[2]), "r"(a[3]), "r"(b[0]), "r"(b[1]));
}

template <int MODE>
__device__ __forceinline__ void gemm_tile(
    const __nv_bfloat16* __restrict__ Ahi, const __nv_bfloat16* __restrict__ Alo,
    const __nv_bfloat16* __restrict__ Bhi, const __nv_bfloat16* __restrict__ Blo,
    const float* __restrict__ bias,
    float* __restrict__ Cf,
    __nv_bfloat16* __restrict__ Chi, __nv_bfloat16* __restrict__ Clo,
    int m0, int n0, int N, int K)
{
    __shared__ __align__(16) __nv_bfloat16 As[2][128][40];
    __shared__ __align__(16) __nv_bfloat16 Bs[2][64][40];

    const int tid  = threadIdx.x;
    const int lane = tid & 31;
    const int wid  = tid >> 5;
    const int wm   = wid & 1;
    const int wn   = wid >> 1;

    float acc[4][2][4];
#pragma unroll
    for (int i = 0; i < 4; i++)
#pragma unroll
        for (int j = 0; j < 2; j++)
#pragma unroll
            for (int k = 0; k < 4; k++) acc[i][j][k] = 0.0f;

    const uint4 zero4 = make_uint4(0, 0, 0, 0);

    for (int kt = 0; kt < K; kt += 32) {
#pragma unroll
        for (int i = 0; i < 2; i++) {
            int it  = tid + i * 256;
            int row = it >> 2;
            int cg  = (it & 3) << 3;
            uint4 vh = zero4, vl = zero4;
            if (kt + cg < K) {
                size_t off = (size_t)(m0 + row) * K + kt + cg;
                vh = *(const uint4*)(Ahi + off);
                vl = *(const uint4*)(Alo + off);
            }
            *(uint4*)&As[0][row][cg] = vh;
            *(uint4*)&As[1][row][cg] = vl;
        }
        {
            int row = tid >> 2;
            int cg  = (tid & 3) << 3;
            uint4 vh = zero4, vl = zero4;
            if (n0 + row < N && kt + cg < K) {
                size_t off = (size_t)(n0 + row) * K + kt + cg;
                vh = *(const uint4*)(Bhi + off);
                vl = *(const uint4*)(Blo + off);
            }
            *(uint4*)&Bs[0][row][cg] = vh;
            *(uint4*)&Bs[1][row][cg] = vl;
        }
        __syncthreads();

#pragma unroll
        for (int ks = 0; ks < 32; ks += 16) {
            uint32_t ah[4][4], al[4][4], bh[4], bl[4];
            int arow = wm * 64 + (lane & 15);
            int acol = ks + ((lane >> 4) << 3);
#pragma unroll
            for (int mi = 0; mi < 4; mi++) {
                ldsm4(ah[mi], (uint32_t)__cvta_generic_to_shared(&As[0][arow + mi * 16][acol]));
                ldsm4(al[mi], (uint32_t)__cvta_generic_to_shared(&As[1][arow + mi * 16][acol]));
            }
            int brow = wn * 16 + (lane & 7) + ((lane >> 4) << 3);
            int bcol = ks + (lane & 8);
            ldsm4(bh, (uint32_t)__cvta_generic_to_shared(&Bs[0][brow][bcol]));
            ldsm4(bl, (uint32_t)__cvta_generic_to_shared(&Bs[1][brow][bcol]));
#pragma unroll
            for (int mi = 0; mi < 4; mi++)
#pragma unroll
                for (int ni = 0; ni < 2; ni++) {
                    mma16816(acc[mi][ni], ah[mi], &bh[ni * 2]);
                    mma16816(acc[mi][ni], ah[mi], &bl[ni * 2]);
                    mma16816(acc[mi][ni], al[mi], &bh[ni * 2]);
                }
        }
        __syncthreads();
    }

    const int g  = lane >> 2;
    const int tg = (lane & 3) << 1;
#pragma unroll
    for (int mi = 0; mi < 4; mi++)
#pragma unroll
        for (int ni = 0; ni < 2; ni++) {
            int col = n0 + wn * 16 + ni * 8 + tg;
            if (col >= N) continue;
#pragma unroll
            for (int hf = 0; hf < 2; hf++) {
                int row = m0 + wm * 64 + mi * 16 + g + hf * 8;
                float v0 = acc[mi][ni][hf * 2 + 0];
                float v1 = acc[mi][ni][hf * 2 + 1];
                if (MODE == 0) {
                    Cf[(size_t)row * N + col]     = v0;
                    Cf[(size_t)row * N + col + 1] = v1;
                } else {
                    v0 += bias[col];
                    v1 += bias[col + 1];
                    if (MODE == 1) {
                        v0 = fmaxf(v0, 0.0f);
                        v1 = fmaxf(v1, 0.0f);
                        __nv_bfloat16 h0, l0, h1, l1;
                        split_bf16(v0, h0, l0);
                        split_bf16(v1, h1, l1);
                        size_t o = (size_t)row * N + col;
                        Chi[o] = h0; Chi[o + 1] = h1;
                        Clo[o] = l0; Clo[o + 1] = l1;
                    } else {
                        Cf[(size_t)row * N + col]     = v0;
                        Cf[(size_t)row * N + col + 1] = v1;
                    }
                }
            }
        }
}

// ---------------------------------------------------------------------------
// GEMM1, all layers: hid = relu(ft @ w1^T + b1). Blocks per layer =
// (8192/128)*(C/64) = C -> cum 64, 192, 448, 960.
// ---------------------------------------------------------------------------
__global__ __launch_bounds__(256) void gemm1_all(InPtrs ip)
{
    int b = blockIdx.x;
    int l = (b < 64) ? 0 : (b < 192) ? 1 : (b < 448) ? 2 : 3;
    const int base[4] = {0, 64, 192, 448};
    int t = b - base[l];
    int C = 64 << l;
    int tilesX = C >> 6;
    int by = t / tilesX, bx = t % tilesX;
    size_t fo = (size_t)8192 * c_cumC[l];
    gemm_tile<1>(g_fthi + fo, g_ftlo + fo,
                 g_whi + c_cumW[l], g_wlo + c_cumW[l], ip.b1[l],
                 nullptr, g_hidhi + fo, g_hidlo + fo,
                 by * 128, bx * 64, C, C);
}

// ---------------------------------------------------------------------------
// GEMM2, all layers: zf = hid @ w2^T + b2. Blocks per layer =
// 64 * ceil(Co/64): 64,64,64,128 -> cum 64, 128, 192, 320.
// ---------------------------------------------------------------------------
__global__ __launch_bounds__(256) void gemm2_all(InPtrs ip)
{
    int b = blockIdx.x;
    int l = (b < 64) ? 0 : (b < 128) ? 1 : (b < 192) ? 2 : 3;
    const int base[4] = {0, 64, 128, 192};
    int t = b - base[l];
    int C = 64 << l, Co = 16 << l;
    int tilesX = (Co + 63) >> 6;
    int by = t / tilesX, bx = t % tilesX;
    size_t fo = (size_t)8192 * c_cumC[l];
    gemm_tile<2>(g_hidhi + fo, g_hidlo + fo,
                 g_whi + c_cumW[l] + C * C, g_wlo + c_cumW[l] + C * C, ip.b2[l],
                 g_zf + (size_t)8192 * c_cumZ[l], nullptr, nullptr,
                 by * 128, bx * 64, Co, C);
}

// ---------------------------------------------------------------------------
// Row L2-normalize all layers: 8192 rows/layer, 8 warp-rows/block ->
// 1024 blocks/layer, 4096 total. Reads fp32 zf, writes split bf16.
// ---------------------------------------------------------------------------
__global__ void norm_all()
{
    int b = blockIdx.x;
    int l = b >> 10;
    int wid = threadIdx.x >> 5, lane = threadIdx.x & 31;
    int row = ((b & 1023) << 3) + wid;
    int Co = 16 << l;
    size_t zo = (size_t)8192 * c_cumZ[l] + (size_t)row * Co;
    const float* r = g_zf + zo;
    float ss = 0.0f;
    for (int j = lane; j < Co; j += 32) {
        float v = r[j];
        ss += v * v;
    }
#pragma unroll
    for (int o = 16; o; o >>= 1) ss += __shfl_xor_sync(0xffffffffu, ss, o);
    float inv = 1.0f / (sqrtf(ss) + 1e-7f);
    for (int j = lane; j < Co; j += 32) {
        float v = r[j] * inv;
        __nv_bfloat16 h, lo;
        split_bf16(v, h, lo);
        g_zhi[zo + j] = h;
        g_zlo[zo + j] = lo;
    }
}

// ---------------------------------------------------------------------------
// Scores, all layers: scores[l][b] = zq[b] @ zk[b]^T  [512x512].
// Blocks per layer = 8 batches * (512/128)*(512/64) = 256 -> 1024 total.
// ---------------------------------------------------------------------------
__global__ __launch_bounds__(256) void scores_all()
{
    int b = blockIdx.x;
    int l = b >> 8;
    int t = b & 255;
    int batch = t >> 5;
    t &= 31;
    int by = t >> 3, bx = t & 7;
    int Co = 16 << l;
    size_t zb = (size_t)8192 * c_cumZ[l];
    const __nv_bfloat16* qhi = g_zhi + zb + (size_t)batch * 512 * Co;
    const __nv_bfloat16* qlo = g_zlo + zb + (size_t)batch * 512 * Co;
    const __nv_bfloat16* khi = g_zhi + zb + (size_t)(4096 + batch * 512) * Co;
    const __nv_bfloat16* klo = g_zlo + zb + (size_t)(4096 + batch * 512) * Co;
    float* out = g_scores + (size_t)l * 2097152 + (size_t)batch * 262144;
    gemm_tile<0>(qhi, qlo, khi, klo, nullptr, out, nullptr, nullptr,
                 by * 128, bx * 64, 512, Co);
}

// ---------------------------------------------------------------------------
// LSE - diag, all layers: 4096 rows/layer, 8 warp-rows/block ->
// 512 blocks/layer, 2048 total.
// ---------------------------------------------------------------------------
__global__ void lse_all()
{
    int b = blockIdx.x;
    int l = b >> 9;
    int bi = b & 511;
    int row = bi * 8 + (threadIdx.x >> 5);
    int lane = threadIdx.x & 31;
    int s = row & 511;
    const float* r = g_scores + (size_t)l * 2097152 + (size_t)row * 512;

    float vals[16];
    float m = -1e30f;
#pragma unroll
    for (int i = 0; i < 16; i++) {
        vals[i] = r[lane + i * 32];
        m = fmaxf(m, vals[i]);
    }
#pragma unroll
    for (int o = 16; o; o >>= 1) m = fmaxf(m, __shfl_xor_sync(0xffffffffu, m, o));

    const float invtau = 1.0f / TAUF;
    float sum = 0.0f;
#pragma unroll
    for (int i = 0; i < 16; i++) sum += __expf((vals[i] - m) * invtau);
#pragma unroll
    for (int o = 16; o; o >>= 1) sum += __shfl_xor_sync(0xffffffffu, sum, o);

    float loss = 0.0f;
    if (lane == 0) {
        float diag = r[s];
        loss = (m - diag) * invtau + logf(sum);
    }

    __shared__ float sh[8];
    if (lane == 0) sh[threadIdx.x >> 5] = loss;
    __syncthreads();
    if (threadIdx.x == 0) {
        float tt = 0.0f;
#pragma unroll
        for (int i = 0; i < 8; i++) tt += sh[i];
        g_partial[l * 512 + bi] = tt;
    }
}

__global__ void final_kernel(float* __restrict__ out)
{
    __shared__ float sh[256];
    float s = 0.0f;
    for (int i = threadIdx.x; i < 4 * 512; i += 256) s += g_partial[i];
    sh[threadIdx.x] = s;
    __syncthreads();
    for (int st = 128; st; st >>= 1) {
        if (threadIdx.x < st) sh[threadIdx.x] += sh[threadIdx.x + st];
        __syncthreads();
    }
    if (threadIdx.x == 0) out[0] = sh[0] / 4096.0f;
}

// ---------------------------------------------------------------------------
extern "C" void kernel_launch(void* const* d_in, const int* in_sizes, int n_in,
                              void* d_out, int out_size)
{
    (void)n_in; (void)out_size;
    bool dict_order = (in_sizes[0] == in_sizes[1]) && (in_sizes[2] == 128);

    InPtrs ip;
    for (int l = 0; l < 4; l++) {
        int ifq, ifk, isid, iw1, ib1, iw2, ib2;
        if (dict_order) {
            int base = 7 * l;
            ifq = base; ifk = base + 1; isid = base + 2;
            iw1 = base + 3; ib1 = base + 4; iw2 = base + 5; ib2 = base + 6;
        } else {
            ifq = l; ifk = 4 + l; isid = 8 + l;
            iw1 = 12 + l * 4; ib1 = iw1 + 1; iw2 = iw1 + 2; ib2 = iw1 + 3;
        }
        ip.fq[l]  = (const float*)d_in[ifq];
        ip.fk[l]  = (const float*)d_in[ifk];
        ip.sid[l] = (const int*)d_in[isid];
        ip.w1[l]  = (const float*)d_in[iw1];
        ip.b1[l]  = (const float*)d_in[ib1];
        ip.w2[l]  = (const float*)d_in[iw2];
        ip.b2[l]  = (const float*)d_in[ib2];
    }

    gather_all<<<30720, 256>>>(ip);
    wconv_all<<<1700, 256>>>(ip);
    gemm1_all<<<960, 256>>>(ip);
    gemm2_all<<<320, 256>>>(ip);
    norm_all<<<4096, 256>>>();
    scores_all<<<1024, 256>>>();
    lse_all<<<2048, 256>>>();
    final_kernel<<<1, 256>>>((float*)d_out);
}

// round 6
// speedup vs baseline: 1.8717x; 1.1626x over previous
#include <cuda_runtime.h>
#include <cuda_bf16.h>
#include <cstdint>
#include <math.h>

// ---------------------------------------------------------------------------
// PatchNCE loss, 4 pyramid layers, stage-batched (one launch per stage).
// GEMMs: bf16x3 split on HMMA, fp32 accum, cp.async 2-stage pipelines.
// Scores stage fuses the LSE exp-sum (fixed shift m=1 since rows are unit
// vectors: v in [-1,1]) -> no 33.5MB scores buffer, no separate LSE pass.
// loss(b,s) = (1 - diag)/tau + log( sum_t exp((v_t - 1)/tau) )
// ---------------------------------------------------------------------------

#define INVTAU 14.285714285714286f

__constant__ int c_cumC[4] = {0, 64, 192, 448};
__constant__ int c_cumZ[4] = {0, 16, 48, 112};
__constant__ int c_cumW[4] = {0, 5120, 25600, 107520};
__constant__ int c_DH[8] = {0, 0, 0, 1, 1, 2, 2, 2};
__constant__ int c_DW[8] = {0, 1, 2, 0, 2, 0, 1, 2};

__device__ __nv_bfloat16 g_fthi[8192 * 960];
__device__ __nv_bfloat16 g_ftlo[8192 * 960];
__device__ __nv_bfloat16 g_hidhi[8192 * 960];
__device__ __nv_bfloat16 g_hidlo[8192 * 960];
__device__ float         g_zf[8192 * 240];
__device__ __nv_bfloat16 g_zhi[8192 * 240];
__device__ __nv_bfloat16 g_zlo[8192 * 240];
__device__ __nv_bfloat16 g_whi[435200];
__device__ __nv_bfloat16 g_wlo[435200];
__device__ float         g_esum[16384 * 8];   // per-row, per-n-tile exp partials
__device__ float         g_diag[16384];
__device__ float         g_partial[64];

struct InPtrs {
    const float* fq[4];
    const float* fk[4];
    const int*   sid[4];
    const float* w1[4];
    const float* b1[4];
    const float* w2[4];
    const float* b2[4];
};

__device__ __forceinline__ void split_bf16(float x, __nv_bfloat16& h, __nv_bfloat16& l)
{
    h = __float2bfloat16(x);
    l = __float2bfloat16(x - __bfloat162float(h));
}

// ---------------------------------------------------------------------------
// Fused gather (blocks 0..30719) + weight conversion (30720..32419).
// ---------------------------------------------------------------------------
__global__ void gw_all(InPtrs ip)
{
    int b = blockIdx.x;
    if (b >= 30720) {
        b -= 30720;
        int l = (b < 20) ? 0 : (b < 100) ? 1 : (b < 420) ? 2 : 3;
        const int wb[4] = {0, 20, 100, 420};
        int C = 64 << l, n1 = C * C;
        int idx = (b - wb[l]) * 256 + threadIdx.x;
        float v = (idx < n1) ? ip.w1[l][idx] : ip.w2[l][idx - n1];
        __nv_bfloat16 hh, ll;
        split_bf16(v, hh, ll);
        g_whi[c_cumW[l] + idx] = hh;
        g_wlo[c_cumW[l] + idx] = ll;
        return;
    }
    int l = (b < 2048) ? 0 : (b < 6144) ? 1 : (b < 14336) ? 2 : 3;
    const int gbase[4] = {0, 2048, 6144, 14336};
    int C = 64 << l, H = 256 >> l, W = H;
    int idx = (b - gbase[l]) * 256 + threadIdx.x;

    int ch = idx % C;
    int n  = idx / C;
    const float* f = (n < 4096) ? ip.fq[l] : ip.fk[l];
    int nl = n & 4095;
    int bb = nl >> 9;
    int s  = nl & 511;
    int sample = s >> 3;
    int nb = s & 7;
    const int* sid = ip.sid[l];
    int h0 = sid[sample * 2 + 0];
    int w0 = sid[sample * 2 + 1];
    int h = h0 + c_DH[nb];
    int w = w0 + c_DW[nb];
    const float* base = f + (size_t)(bb * C + ch) * H * W;
    float v = base[h * W + w] - base[(h0 + 1) * W + (w0 + 1)];
    __nv_bfloat16 hh, ll;
    split_bf16(v, hh, ll);
    size_t off = (size_t)8192 * c_cumC[l] + (size_t)n * C + ch;
    g_fthi[off] = hh;
    g_ftlo[off] = ll;
}

// ---------------------------------------------------------------------------
// MMA / cp.async primitives
// ---------------------------------------------------------------------------
__device__ __forceinline__ void ldsm4(uint32_t* r, uint32_t saddr)
{
    asm volatile("ldmatrix.sync.aligned.m8n8.x4.shared.b16 {%0,%1,%2,%3}, [%4];"
                 : "=r"(r[0]), "=r"(r[1]), "=r"(r[2]), "=r"(r[3])
                 : "r"(saddr));
}

__device__ __forceinline__ void mma16816(float* c, const uint32_t* a, const uint32_t* b)
{
    asm volatile(
        "mma.sync.aligned.m16n8k16.row.col.f32.bf16.bf16.f32 "
        "{%0,%1,%2,%3}, {%4,%5,%6,%7}, {%8,%9}, {%0,%1,%2,%3};"
        : "+f"(c[0]), "+f"(c[1]), "+f"(c[2]), "+f"(c[3])
        : "r"(a[0]), "r"(a[1]), "r"(a[2]), "r"(a[3]), "r"(b[0]), "r"(b[1]));
}

__device__ __forceinline__ void cpa16(uint32_t dst, const void* src, bool p)
{
    int sz = p ? 16 : 0;
    asm volatile("cp.async.cg.shared.global [%0], [%1], 16, %2;\n"
                 :: "r"(dst), "l"(src), "r"(sz));
}
#define CP_COMMIT() asm volatile("cp.async.commit_group;\n")
#define CP_WAIT0()  asm volatile("cp.async.wait_group 0;\n")
#define CP_WAIT1()  asm volatile("cp.async.wait_group 1;\n")

// Stage loaders. Tiles padded to 40 halfs/row; zero-fill beyond K via cp.async.
__device__ __forceinline__ void loadA128(__nv_bfloat16 (*As)[128][40],
    const __nv_bfloat16* Ahi, const __nv_bfloat16* Alo, int m0, int K, int kt, int tid)
{
#pragma unroll
    for (int i = 0; i < 2; i++) {
        int it = tid + i * 256, row = it >> 2, cg = (it & 3) << 3;
        bool p = (kt + cg) < K;
        size_t off = (size_t)(m0 + row) * K + kt + cg;
        cpa16((uint32_t)__cvta_generic_to_shared(&As[0][row][cg]),
              p ? (const void*)(Ahi + off) : (const void*)Ahi, p);
        cpa16((uint32_t)__cvta_generic_to_shared(&As[1][row][cg]),
              p ? (const void*)(Alo + off) : (const void*)Alo, p);
    }
}
__device__ __forceinline__ void load64(__nv_bfloat16 (*Bs)[64][40],
    const __nv_bfloat16* Bhi, const __nv_bfloat16* Blo, int n0, int N, int K, int kt, int tid)
{
    int row = tid >> 2, cg = (tid & 3) << 3;
    bool p = (n0 + row) < N && (kt + cg) < K;
    size_t off = (size_t)(n0 + row) * K + kt + cg;
    cpa16((uint32_t)__cvta_generic_to_shared(&Bs[0][row][cg]),
          p ? (const void*)(Bhi + off) : (const void*)Bhi, p);
    cpa16((uint32_t)__cvta_generic_to_shared(&Bs[1][row][cg]),
          p ? (const void*)(Blo + off) : (const void*)Blo, p);
}

// ---------------------------------------------------------------------------
// 128x64 tile GEMM (NT), bf16x3, 2-stage cp.async pipeline. 8 warps: 2m x 4n.
// MODE 1: +bias, relu, split-bf16 store (gemm1).
// MODE 3: scores epilogue -> per-row exp-sum partials + diag (no C store).
// ---------------------------------------------------------------------------
template <int MODE>
__device__ void gemm128(
    const __nv_bfloat16* __restrict__ Ahi, const __nv_bfloat16* __restrict__ Alo,
    const __nv_bfloat16* __restrict__ Bhi, const __nv_bfloat16* __restrict__ Blo,
    const float* __restrict__ bias,
    __nv_bfloat16* __restrict__ Chi, __nv_bfloat16* __restrict__ Clo,
    float* __restrict__ esum, float* __restrict__ diag, int bxi,
    int m0, int n0, int N, int K)
{
    __shared__ __align__(16) __nv_bfloat16 As[2][2][128][40];
    __shared__ __align__(16) __nv_bfloat16 Bs[2][2][64][40];
    __shared__ float s_red[4][128];

    const int tid = threadIdx.x, lane = tid & 31, wid = tid >> 5;
    const int wm = wid & 1, wn = wid >> 1;

    float acc[4][2][4];
#pragma unroll
    for (int i = 0; i < 4; i++)
#pragma unroll
        for (int j = 0; j < 2; j++)
#pragma unroll
            for (int k = 0; k < 4; k++) acc[i][j][k] = 0.0f;

    const int nk = (K + 31) >> 5;
    loadA128(As[0], Ahi, Alo, m0, K, 0, tid);
    load64(Bs[0], Bhi, Blo, n0, N, K, 0, tid);
    CP_COMMIT();

    int st = 0;
    for (int it = 0; it < nk; it++) {
        if (it + 1 < nk) {
            loadA128(As[st ^ 1], Ahi, Alo, m0, K, (it + 1) * 32, tid);
            load64(Bs[st ^ 1], Bhi, Blo, n0, N, K, (it + 1) * 32, tid);
            CP_COMMIT();
            CP_WAIT1();
        } else {
            CP_WAIT0();
        }
        __syncthreads();

#pragma unroll
        for (int ks = 0; ks < 32; ks += 16) {
            uint32_t ah[4][4], al[4][4], bh[4], bl[4];
            int arow = wm * 64 + (lane & 15);
            int acol = ks + ((lane >> 4) << 3);
#pragma unroll
            for (int mi = 0; mi < 4; mi++) {
                ldsm4(ah[mi], (uint32_t)__cvta_generic_to_shared(&As[st][0][arow + mi * 16][acol]));
                ldsm4(al[mi], (uint32_t)__cvta_generic_to_shared(&As[st][1][arow + mi * 16][acol]));
            }
            int brow = wn * 16 + (lane & 7) + ((lane >> 4) << 3);
            int bcol = ks + (lane & 8);
            ldsm4(bh, (uint32_t)__cvta_generic_to_shared(&Bs[st][0][brow][bcol]));
            ldsm4(bl, (uint32_t)__cvta_generic_to_shared(&Bs[st][1][brow][bcol]));
#pragma unroll
            for (int mi = 0; mi < 4; mi++)
#pragma unroll
                for (int ni = 0; ni < 2; ni++) {
                    mma16816(acc[mi][ni], ah[mi], &bh[ni * 2]);
                    mma16816(acc[mi][ni], ah[mi], &bl[ni * 2]);
                    mma16816(acc[mi][ni], al[mi], &bh[ni * 2]);
                }
        }
        __syncthreads();
        st ^= 1;
    }

    const int g  = lane >> 2;
    const int tg = (lane & 3) << 1;

    if (MODE == 1) {
#pragma unroll
        for (int mi = 0; mi < 4; mi++)
#pragma unroll
            for (int ni = 0; ni < 2; ni++) {
                int col = n0 + wn * 16 + ni * 8 + tg;
                if (col >= N) continue;
#pragma unroll
                for (int hf = 0; hf < 2; hf++) {
                    int row = m0 + wm * 64 + mi * 16 + g + hf * 8;
                    float v0 = fmaxf(acc[mi][ni][hf * 2 + 0] + bias[col], 0.0f);
                    float v1 = fmaxf(acc[mi][ni][hf * 2 + 1] + bias[col + 1], 0.0f);
                    __nv_bfloat16 h0, l0, h1, l1;
                    split_bf16(v0, h0, l0);
                    split_bf16(v1, h1, l1);
                    size_t o = (size_t)row * N + col;
                    Chi[o] = h0; Chi[o + 1] = h1;
                    Clo[o] = l0; Clo[o + 1] = l1;
                }
            }
    } else {  // MODE 3: fused exp-sum + diag extraction (N==512 full tile)
#pragma unroll
        for (int mi = 0; mi < 4; mi++)
#pragma unroll
            for (int hf = 0; hf < 2; hf++) {
                int rloc = wm * 64 + mi * 16 + hf * 8 + g;
                int r = m0 + rloc;
                float s = 0.0f;
#pragma unroll
                for (int ni = 0; ni < 2; ni++)
#pragma unroll
                    for (int j = 0; j < 2; j++) {
                        float v = acc[mi][ni][hf * 2 + j];
                        int c = n0 + wn * 16 + ni * 8 + tg + j;
                        if (c == r) diag[r] = v;
                        s += __expf((v - 1.0f) * INVTAU);
                    }
                s += __shfl_xor_sync(0xffffffffu, s, 1);
                s += __shfl_xor_sync(0xffffffffu, s, 2);
                if ((lane & 3) == 0) s_red[wn][rloc] = s;
            }
        __syncthreads();
        if (tid < 128) {
            float t = s_red[0][tid] + s_red[1][tid] + s_red[2][tid] + s_red[3][tid];
            esum[(size_t)(m0 + tid) * 8 + bxi] = t;
        }
    }
}

// ---------------------------------------------------------------------------
// 64x64 tile GEMM (gemm2: +bias, fp32 store). 8 warps: 2m x 4n, warp 32x16.
// 40KB smem, ~4 CTA/SM -> better latency hiding + wave balance.
// ---------------------------------------------------------------------------
__device__ void gemm64(
    const __nv_bfloat16* __restrict__ Ahi, const __nv_bfloat16* __restrict__ Alo,
    const __nv_bfloat16* __restrict__ Bhi, const __nv_bfloat16* __restrict__ Blo,
    const float* __restrict__ bias, float* __restrict__ Cf,
    int m0, int n0, int N, int K)
{
    __shared__ __align__(16) __nv_bfloat16 As[2][2][64][40];
    __shared__ __align__(16) __nv_bfloat16 Bs[2][2][64][40];

    const int tid = threadIdx.x, lane = tid & 31, wid = tid >> 5;
    const int wm = wid & 1, wn = wid >> 1;

    float acc[2][2][4];
#pragma unroll
    for (int i = 0; i < 2; i++)
#pragma unroll
        for (int j = 0; j < 2; j++)
#pragma unroll
            for (int k = 0; k < 4; k++) acc[i][j][k] = 0.0f;

    const int nk = (K + 31) >> 5;
    load64(As[0], Ahi, Alo, m0, 1 << 30, K, 0, tid);
    load64(Bs[0], Bhi, Blo, n0, N, K, 0, tid);
    CP_COMMIT();

    int st = 0;
    for (int it = 0; it < nk; it++) {
        if (it + 1 < nk) {
            load64(As[st ^ 1], Ahi, Alo, m0, 1 << 30, K, (it + 1) * 32, tid);
            load64(Bs[st ^ 1], Bhi, Blo, n0, N, K, (it + 1) * 32, tid);
            CP_COMMIT();
            CP_WAIT1();
        } else {
            CP_WAIT0();
        }
        __syncthreads();

#pragma unroll
        for (int ks = 0; ks < 32; ks += 16) {
            uint32_t ah[2][4], al[2][4], bh[4], bl[4];
            int arow = wm * 32 + (lane & 15);
            int acol = ks + ((lane >> 4) << 3);
#pragma unroll
            for (int mi = 0; mi < 2; mi++) {
                ldsm4(ah[mi], (uint32_t)__cvta_generic_to_shared(&As[st][0][arow + mi * 16][acol]));
                ldsm4(al[mi], (uint32_t)__cvta_generic_to_shared(&As[st][1][arow + mi * 16][acol]));
            }
            int brow = wn * 16 + (lane & 7) + ((lane >> 4) << 3);
            int bcol = ks + (lane & 8);
            ldsm4(bh, (uint32_t)__cvta_generic_to_shared(&Bs[st][0][brow][bcol]));
            ldsm4(bl, (uint32_t)__cvta_generic_to_shared(&Bs[st][1][brow][bcol]));
#pragma unroll
            for (int mi = 0; mi < 2; mi++)
#pragma unroll
                for (int ni = 0; ni < 2; ni++) {
                    mma16816(acc[mi][ni], ah[mi], &bh[ni * 2]);
                    mma16816(acc[mi][ni], ah[mi], &bl[ni * 2]);
                    mma16816(acc[mi][ni], al[mi], &bh[ni * 2]);
                }
        }
        __syncthreads();
        st ^= 1;
    }

    const int g  = lane >> 2;
    const int tg = (lane & 3) << 1;
#pragma unroll
    for (int mi = 0; mi < 2; mi++)
#pragma unroll
        for (int ni = 0; ni < 2; ni++) {
            int col = n0 + wn * 16 + ni * 8 + tg;
            if (col >= N) continue;
#pragma unroll
            for (int hf = 0; hf < 2; hf++) {
                int row = m0 + wm * 32 + mi * 16 + g + hf * 8;
                Cf[(size_t)row * N + col]     = acc[mi][ni][hf * 2 + 0] + bias[col];
                Cf[(size_t)row * N + col + 1] = acc[mi][ni][hf * 2 + 1] + bias[col + 1];
            }
        }
}

// ---------------------------------------------------------------------------
// GEMM1: hid = relu(ft @ w1^T + b1). Blocks/layer = C -> cum 64,192,448,960.
// ---------------------------------------------------------------------------
__global__ __launch_bounds__(256) void gemm1_all(InPtrs ip)
{
    int b = blockIdx.x;
    int l = (b < 64) ? 0 : (b < 192) ? 1 : (b < 448) ? 2 : 3;
    const int base[4] = {0, 64, 192, 448};
    int t = b - base[l];
    int C = 64 << l;
    int tilesX = C >> 6;
    int by = t / tilesX, bx = t % tilesX;
    size_t fo = (size_t)8192 * c_cumC[l];
    gemm128<1>(g_fthi + fo, g_ftlo + fo, g_whi + c_cumW[l], g_wlo + c_cumW[l],
               ip.b1[l], g_hidhi + fo, g_hidlo + fo, nullptr, nullptr, 0,
               by * 128, bx * 64, C, C);
}

// ---------------------------------------------------------------------------
// GEMM2: zf = hid @ w2^T + b2. 64-row tiles: blocks 128,128,128,256 -> 640.
// ---------------------------------------------------------------------------
__global__ __launch_bounds__(256) void gemm2_all(InPtrs ip)
{
    int b = blockIdx.x;
    int l = (b < 128) ? 0 : (b < 256) ? 1 : (b < 384) ? 2 : 3;
    const int base[4] = {0, 128, 256, 384};
    int t = b - base[l];
    int C = 64 << l, Co = 16 << l;
    int tilesX = (Co + 63) >> 6;
    int by = t / tilesX, bx = t % tilesX;
    size_t fo = (size_t)8192 * c_cumC[l];
    gemm64(g_hidhi + fo, g_hidlo + fo,
           g_whi + c_cumW[l] + C * C, g_wlo + c_cumW[l] + C * C,
           ip.b2[l], g_zf + (size_t)8192 * c_cumZ[l],
           by * 64, bx * 64, Co, C);
}

// ---------------------------------------------------------------------------
// Row L2-normalize: 8 warp-rows/block, 1024 blocks/layer -> 4096.
// ---------------------------------------------------------------------------
__global__ void norm_all()
{
    int b = blockIdx.x;
    int l = b >> 10;
    int wid = threadIdx.x >> 5, lane = threadIdx.x & 31;
    int row = ((b & 1023) << 3) + wid;
    int Co = 16 << l;
    size_t zo = (size_t)8192 * c_cumZ[l] + (size_t)row * Co;
    const float* r = g_zf + zo;
    float ss = 0.0f;
    for (int j = lane; j < Co; j += 32) {
        float v = r[j];
        ss += v * v;
    }
#pragma unroll
    for (int o = 16; o; o >>= 1) ss += __shfl_xor_sync(0xffffffffu, ss, o);
    float inv = 1.0f / (sqrtf(ss) + 1e-7f);
    for (int j = lane; j < Co; j += 32) {
        float v = r[j] * inv;
        __nv_bfloat16 h, lo;
        split_bf16(v, h, lo);
        g_zhi[zo + j] = h;
        g_zlo[zo + j] = lo;
    }
}

// ---------------------------------------------------------------------------
// Scores + fused exp-sum: 8 batch x 4 by x 8 bx = 256 blocks/layer -> 1024.
// ---------------------------------------------------------------------------
__global__ __launch_bounds__(256) void scores_all()
{
    int b = blockIdx.x;
    int l = b >> 8;
    int t = b & 255;
    int batch = t >> 5;
    t &= 31;
    int by = t >> 3, bx = t & 7;
    int Co = 16 << l;
    size_t zb = (size_t)8192 * c_cumZ[l];
    const __nv_bfloat16* qhi = g_zhi + zb + (size_t)batch * 512 * Co;
    const __nv_bfloat16* qlo = g_zlo + zb + (size_t)batch * 512 * Co;
    const __nv_bfloat16* khi = g_zhi + zb + (size_t)(4096 + batch * 512) * Co;
    const __nv_bfloat16* klo = g_zlo + zb + (size_t)(4096 + batch * 512) * Co;
    float* esum = g_esum + (size_t)(l * 8 + batch) * 512 * 8;
    float* diag = g_diag + (size_t)(l * 8 + batch) * 512;
    gemm128<3>(qhi, qlo, khi, klo, nullptr, nullptr, nullptr,
               esum, diag, bx, by * 128, bx * 64, 512, Co);
}

// ---------------------------------------------------------------------------
// Final LSE combine: 16384 rows. loss = (1-diag)/tau + log(sum of 8 partials).
// ---------------------------------------------------------------------------
__global__ void lse_final()
{
    int row = blockIdx.x * 256 + threadIdx.x;
    float s = 0.0f;
#pragma unroll
    for (int i = 0; i < 8; i++) s += g_esum[(size_t)row * 8 + i];
    float loss = (1.0f - g_diag[row]) * INVTAU + logf(s);
    __shared__ float sh[256];
    sh[threadIdx.x] = loss;
    __syncthreads();
    for (int st = 128; st; st >>= 1) {
        if (threadIdx.x < st) sh[threadIdx.x] += sh[threadIdx.x + st];
        __syncthreads();
    }
    if (threadIdx.x == 0) g_partial[blockIdx.x] = sh[0];
}

__global__ void final_kernel(float* __restrict__ out)
{
    __shared__ float sh[64];
    if (threadIdx.x < 64) sh[threadIdx.x] = g_partial[threadIdx.x];
    __syncthreads();
    if (threadIdx.x == 0) {
        float s = 0.0f;
        for (int i = 0; i < 64; i++) s += sh[i];
        out[0] = s / 4096.0f;
    }
}

// ---------------------------------------------------------------------------
extern "C" void kernel_launch(void* const* d_in, const int* in_sizes, int n_in,
                              void* d_out, int out_size)
{
    (void)n_in; (void)out_size;
    bool dict_order = (in_sizes[0] == in_sizes[1]) && (in_sizes[2] == 128);

    InPtrs ip;
    for (int l = 0; l < 4; l++) {
        int ifq, ifk, isid, iw1, ib1, iw2, ib2;
        if (dict_order) {
            int base = 7 * l;
            ifq = base; ifk = base + 1; isid = base + 2;
            iw1 = base + 3; ib1 = base + 4; iw2 = base + 5; ib2 = base + 6;
        } else {
            ifq = l; ifk = 4 + l; isid = 8 + l;
            iw1 = 12 + l * 4; ib1 = iw1 + 1; iw2 = iw1 + 2; ib2 = iw1 + 3;
        }
        ip.fq[l]  = (const float*)d_in[ifq];
        ip.fk[l]  = (const float*)d_in[ifk];
        ip.sid[l] = (const int*)d_in[isid];
        ip.w1[l]  = (const float*)d_in[iw1];
        ip.b1[l]  = (const float*)d_in[ib1];
        ip.w2[l]  = (const float*)d_in[iw2];
        ip.b2[l]  = (const float*)d_in[ib2];
    }

    gw_all<<<32420, 256>>>(ip);
    gemm1_all<<<960, 256>>>(ip);
    gemm2_all<<<640, 256>>>(ip);
    norm_all<<<4096, 256>>>();
    scores_all<<<1024, 256>>>();
    lse_final<<<64, 256>>>();
    final_kernel<<<1, 256>>>((float*)d_out);
}

// round 8
// speedup vs baseline: 2.3369x; 1.2486x over previous
#include <cuda_runtime.h>
#include <cuda_bf16.h>
#include <cstdint>
#include <math.h>

// ---------------------------------------------------------------------------
// PatchNCE loss, 4 pyramid layers, stage-batched.
// GEMMs: bf16x3 split on HMMA, fp32 accum, cp.async 2-stage pipelines.
// Gather: patch-based (9 loads -> 8 outputs) with float4 loads, packed stores.
// gemm2 fuses the row L2-norm for Co<=64 (layers 0-2).
// Scores stage fuses the LSE exp-sum (fixed shift m=1; rows are unit vectors).
// loss(b,s) = (1 - diag)/tau + log( sum_t exp((v_t - 1)/tau) )
// ---------------------------------------------------------------------------

#define INVTAU 14.285714285714286f

__constant__ int c_cumC[4] = {0, 64, 192, 448};
__constant__ int c_cumZ[4] = {0, 16, 48, 112};
__constant__ int c_cumW[4] = {0, 5120, 25600, 107520};

__device__ __nv_bfloat16 g_fthi[8192 * 960];
__device__ __nv_bfloat16 g_ftlo[8192 * 960];
__device__ __nv_bfloat16 g_hidhi[8192 * 960];
__device__ __nv_bfloat16 g_hidlo[8192 * 960];
__device__ float         g_zf[8192 * 128];     // layer-3 pre-norm only
__device__ __nv_bfloat16 g_zhi[8192 * 240];
__device__ __nv_bfloat16 g_zlo[8192 * 240];
__device__ __nv_bfloat16 g_whi[435200];
__device__ __nv_bfloat16 g_wlo[435200];
__device__ float         g_esum[16384 * 8];
__device__ float         g_diag[16384];
__device__ float         g_partial[64];

struct InPtrs {
    const float* fq[4];
    const float* fk[4];
    const int*   sid[4];
    const float* w1[4];
    const float* b1[4];
    const float* w2[4];
    const float* b2[4];
};

__device__ __forceinline__ void split_bf16(float x, __nv_bfloat16& h, __nv_bfloat16& l)
{
    h = __float2bfloat16(x);
    l = __float2bfloat16(x - __bfloat162float(h));
}

// ---------------------------------------------------------------------------
// Gather (blocks 0..959) + weight conversion (960..2659).
// Gather: thread = (layer, tensor, b, sample, 4-channel group). Loads the
// 3x3 patch per channel via 1-2 aligned float4 per row (w0&3 uniform),
// emits 8 neighbor-center diffs, packed uint2 (4x bf16) stores per neighbor.
// ---------------------------------------------------------------------------
__global__ __launch_bounds__(256) void gw_all(InPtrs ip)
{
    int b = blockIdx.x;
    if (b >= 960) {   // weight conversion
        b -= 960;
        int l = (b < 20) ? 0 : (b < 100) ? 1 : (b < 420) ? 2 : 3;
        const int wb[4] = {0, 20, 100, 420};
        int C = 64 << l, n1 = C * C;
        int idx = (b - wb[l]) * 256 + threadIdx.x;
        float v = (idx < n1) ? ip.w1[l][idx] : ip.w2[l][idx - n1];
        __nv_bfloat16 hh, ll;
        split_bf16(v, hh, ll);
        g_whi[c_cumW[l] + idx] = hh;
        g_wlo[c_cumW[l] + idx] = ll;
        return;
    }
    int l = (b < 64) ? 0 : (b < 192) ? 1 : (b < 448) ? 2 : 3;
    const int gbase[4] = {0, 64, 192, 448};
    int t = b - gbase[l];
    const int C = 64 << l, H = 256 >> l, W = H, HW = H * W;
    const int TOT = (C << 3) * HW;          // 8*C*H*W (= 33554432 each layer)
    int gi = t * 256 + threadIdx.x;
    int shp = 4 + l;                         // log2(C/4)
    int token = gi >> shp;                   // 0..1023
    int cg = gi & ((1 << shp) - 1);
    int tensor = token >> 9;
    int bs = token & 511;                    // b*64 + sample
    int bb = bs >> 6, sample = bs & 63;
    int c0 = cg << 2;

    const float* f = tensor ? ip.fk[l] : ip.fq[l];
    const int* sid = ip.sid[l];
    int h0 = sid[sample * 2 + 0];
    int w0 = sid[sample * 2 + 1];
    int o = w0 & 3;

    float v[4][3][3];
#pragma unroll
    for (int cc = 0; cc < 4; cc++) {
        int plane = (bb * C + c0 + cc) * HW;
#pragma unroll
        for (int r = 0; r < 3; r++) {
            int p = plane + (h0 + r) * W + w0;
            int a = p & ~3;
            float4 q0 = __ldg((const float4*)f + (a >> 2));
            float x0, x1, x2;
            if (o == 0)      { x0 = q0.x; x1 = q0.y; x2 = q0.z; }
            else if (o == 1) { x0 = q0.y; x1 = q0.z; x2 = q0.w; }
            else {
                if (a + 8 <= TOT) {
                    float4 q1 = __ldg((const float4*)f + (a >> 2) + 1);
                    if (o == 2) { x0 = q0.z; x1 = q0.w; x2 = q1.x; }
                    else        { x0 = q0.w; x1 = q1.x; x2 = q1.y; }
                } else {
                    x0 = __ldg(f + p); x1 = __ldg(f + p + 1); x2 = __ldg(f + p + 2);
                }
            }
            v[cc][r][0] = x0; v[cc][r][1] = x1; v[cc][r][2] = x2;
        }
    }

    const int dh[8] = {0, 0, 0, 1, 1, 2, 2, 2};
    const int dw[8] = {0, 1, 2, 0, 2, 0, 1, 2};
    __nv_bfloat16 ph[8][4], pl[8][4];
#pragma unroll
    for (int cc = 0; cc < 4; cc++) {
        float ctr = v[cc][1][1];
#pragma unroll
        for (int nb = 0; nb < 8; nb++) {
            float d = v[cc][dh[nb]][dw[nb]] - ctr;
            split_bf16(d, ph[nb][cc], pl[nb][cc]);
        }
    }

    size_t rowBase = (size_t)8192 * c_cumC[l] +
                     ((size_t)tensor * 4096 + (size_t)bs * 8) * C + c0;
#pragma unroll
    for (int nb = 0; nb < 8; nb++) {
        size_t off = rowBase + (size_t)nb * C;
        *(uint2*)(g_fthi + off) = *(const uint2*)&ph[nb][0];
        *(uint2*)(g_ftlo + off) = *(const uint2*)&pl[nb][0];
    }
}

// ---------------------------------------------------------------------------
// MMA / cp.async primitives
// ---------------------------------------------------------------------------
__device__ __forceinline__ void ldsm4(uint32_t* r, uint32_t saddr)
{
    asm volatile("ldmatrix.sync.aligned.m8n8.x4.shared.b16 {%0,%1,%2,%3}, [%4];"
                 : "=r"(r[0]), "=r"(r[1]), "=r"(r[2]), "=r"(r[3])
                 : "r"(saddr));
}

__device__ __forceinline__ void mma16816(float* c, const uint32_t* a, const uint32_t* b)
{
    asm volatile(
        "mma.sync.aligned.m16n8k16.row.col.f32.bf16.bf16.f32 "
        "{%0,%1,%2,%3}, {%4,%5,%6,%7}, {%8,%9}, {%0,%1,%2,%3};"
        : "+f"(c[0]), "+f"(c[1]), "+f"(c[2]), "+f"(c[3])
        : "r"(a[0]), "r"(a[1]), "r"(a[2]), "r"(a[3]), "r"(b[0]), "r"(b[1]));
}

__device__ __forceinline__ void cpa16(uint32_t dst, const void* src, bool p)
{
    int sz = p ? 16 : 0;
    asm volatile("cp.async.cg.shared.global [%0], [%1], 16, %2;\n"
                 :: "r"(dst), "l"(src), "r"(sz));
}
#define CP_COMMIT() asm volatile("cp.async.commit_group;\n")
#define CP_WAIT0()  asm volatile("cp.async.wait_group 0;\n")
#define CP_WAIT1()  asm volatile("cp.async.wait_group 1;\n")

__device__ __forceinline__ void loadA128(__nv_bfloat16 (*As)[128][40],
    const __nv_bfloat16* Ahi, const __nv_bfloat16* Alo, int m0, int K, int kt, int tid)
{
#pragma unroll
    for (int i = 0; i < 2; i++) {
        int it = tid + i * 256, row = it >> 2, cg = (it & 3) << 3;
        bool p = (kt + cg) < K;
        size_t off = (size_t)(m0 + row) * K + kt + cg;
        cpa16((uint32_t)__cvta_generic_to_shared(&As[0][row][cg]),
              p ? (const void*)(Ahi + off) : (const void*)Ahi, p);
        cpa16((uint32_t)__cvta_generic_to_shared(&As[1][row][cg]),
              p ? (const void*)(Alo + off) : (const void*)Alo, p);
    }
}
__device__ __forceinline__ void load64(__nv_bfloat16 (*Bs)[64][40],
    const __nv_bfloat16* Bhi, const __nv_bfloat16* Blo, int n0, int N, int K, int kt, int tid)
{
    int row = tid >> 2, cg = (tid & 3) << 3;
    bool p = (n0 + row) < N && (kt + cg) < K;
    size_t off = (size_t)(n0 + row) * K + kt + cg;
    cpa16((uint32_t)__cvta_generic_to_shared(&Bs[0][row][cg]),
          p ? (const void*)(Bhi + off) : (const void*)Bhi, p);
    cpa16((uint32_t)__cvta_generic_to_shared(&Bs[1][row][cg]),
          p ? (const void*)(Blo + off) : (const void*)Blo, p);
}

// ---------------------------------------------------------------------------
// 128x64 tile GEMM (NT), bf16x3, 2-stage pipeline. 8 warps: 2m x 4n.
// MODE 1: +bias, relu, split-bf16 store (gemm1).
// MODE 3: scores epilogue -> per-row exp-sum partials + diag.
// ---------------------------------------------------------------------------
template <int MODE>
__device__ void gemm128(
    const __nv_bfloat16* __restrict__ Ahi, const __nv_bfloat16* __restrict__ Alo,
    const __nv_bfloat16* __restrict__ Bhi, const __nv_bfloat16* __restrict__ Blo,
    const float* __restrict__ bias,
    __nv_bfloat16* __restrict__ Chi, __nv_bfloat16* __restrict__ Clo,
    float* __restrict__ esum, float* __restrict__ diag, int bxi,
    int m0, int n0, int N, int K)
{
    __shared__ __align__(16) __nv_bfloat16 As[2][2][128][40];
    __shared__ __align__(16) __nv_bfloat16 Bs[2][2][64][40];
    __shared__ float s_red[4][128];

    const int tid = threadIdx.x, lane = tid & 31, wid = tid >> 5;
    const int wm = wid & 1, wn = wid >> 1;

    float acc[4][2][4];
#pragma unroll
    for (int i = 0; i < 4; i++)
#pragma unroll
        for (int j = 0; j < 2; j++)
#pragma unroll
            for (int k = 0; k < 4; k++) acc[i][j][k] = 0.0f;

    const int nk = (K + 31) >> 5;
    loadA128(As[0], Ahi, Alo, m0, K, 0, tid);
    load64(Bs[0], Bhi, Blo, n0, N, K, 0, tid);
    CP_COMMIT();

    int st = 0;
    for (int it = 0; it < nk; it++) {
        if (it + 1 < nk) {
            loadA128(As[st ^ 1], Ahi, Alo, m0, K, (it + 1) * 32, tid);
            load64(Bs[st ^ 1], Bhi, Blo, n0, N, K, (it + 1) * 32, tid);
            CP_COMMIT();
            CP_WAIT1();
        } else {
            CP_WAIT0();
        }
        __syncthreads();

#pragma unroll
        for (int ks = 0; ks < 32; ks += 16) {
            uint32_t ah[4][4], al[4][4], bh[4], bl[4];
            int arow = wm * 64 + (lane & 15);
            int acol = ks + ((lane >> 4) << 3);
#pragma unroll
            for (int mi = 0; mi < 4; mi++) {
                ldsm4(ah[mi], (uint32_t)__cvta_generic_to_shared(&As[st][0][arow + mi * 16][acol]));
                ldsm4(al[mi], (uint32_t)__cvta_generic_to_shared(&As[st][1][arow + mi * 16][acol]));
            }
            int brow = wn * 16 + (lane & 7) + ((lane >> 4) << 3);
            int bcol = ks + (lane & 8);
            ldsm4(bh, (uint32_t)__cvta_generic_to_shared(&Bs[st][0][brow][bcol]));
            ldsm4(bl, (uint32_t)__cvta_generic_to_shared(&Bs[st][1][brow][bcol]));
#pragma unroll
            for (int mi = 0; mi < 4; mi++)
#pragma unroll
                for (int ni = 0; ni < 2; ni++) {
                    mma16816(acc[mi][ni], ah[mi], &bh[ni * 2]);
                    mma16816(acc[mi][ni], ah[mi], &bl[ni * 2]);
                    mma16816(acc[mi][ni], al[mi], &bh[ni * 2]);
                }
        }
        __syncthreads();
        st ^= 1;
    }

    const int g  = lane >> 2;
    const int tg = (lane & 3) << 1;

    if (MODE == 1) {
#pragma unroll
        for (int mi = 0; mi < 4; mi++)
#pragma unroll
            for (int ni = 0; ni < 2; ni++) {
                int col = n0 + wn * 16 + ni * 8 + tg;
                if (col >= N) continue;
#pragma unroll
                for (int hf = 0; hf < 2; hf++) {
                    int row = m0 + wm * 64 + mi * 16 + g + hf * 8;
                    float v0 = fmaxf(acc[mi][ni][hf * 2 + 0] + bias[col], 0.0f);
                    float v1 = fmaxf(acc[mi][ni][hf * 2 + 1] + bias[col + 1], 0.0f);
                    __nv_bfloat16 h0, l0, h1, l1;
                    split_bf16(v0, h0, l0);
                    split_bf16(v1, h1, l1);
                    size_t o = (size_t)row * N + col;
                    Chi[o] = h0; Chi[o + 1] = h1;
                    Clo[o] = l0; Clo[o + 1] = l1;
                }
            }
    } else {  // MODE 3: fused exp-sum + diag (full 512-col row via 8 bx tiles)
#pragma unroll
        for (int mi = 0; mi < 4; mi++)
#pragma unroll
            for (int hf = 0; hf < 2; hf++) {
                int rloc = wm * 64 + mi * 16 + hf * 8 + g;
                int r = m0 + rloc;
                float s = 0.0f;
#pragma unroll
                for (int ni = 0; ni < 2; ni++)
#pragma unroll
                    for (int j = 0; j < 2; j++) {
                        float v = acc[mi][ni][hf * 2 + j];
                        int c = n0 + wn * 16 + ni * 8 + tg + j;
                        if (c == r) diag[r] = v;
                        s += __expf((v - 1.0f) * INVTAU);
                    }
                s += __shfl_xor_sync(0xffffffffu, s, 1);
                s += __shfl_xor_sync(0xffffffffu, s, 2);
                if ((lane & 3) == 0) s_red[wn][rloc] = s;
            }
        __syncthreads();
        if (tid < 128) {
            float t = s_red[0][tid] + s_red[1][tid] + s_red[2][tid] + s_red[3][tid];
            esum[(size_t)(m0 + tid) * 8 + bxi] = t;
        }
    }
}

// ---------------------------------------------------------------------------
// 64x64 tile GEMM (gemm2). MODE2 0: +bias -> fp32 Cf (layer 3).
// MODE2 1: +bias, fused row-L2-norm, split-bf16 -> Zhi/Zlo (Co<=64, n0=0).
// ---------------------------------------------------------------------------
template <int MODE2>
__device__ void gemm64(
    const __nv_bfloat16* __restrict__ Ahi, const __nv_bfloat16* __restrict__ Alo,
    const __nv_bfloat16* __restrict__ Bhi, const __nv_bfloat16* __restrict__ Blo,
    const float* __restrict__ bias, float* __restrict__ Cf,
    __nv_bfloat16* __restrict__ Zhi, __nv_bfloat16* __restrict__ Zlo,
    int m0, int n0, int N, int K)
{
    __shared__ __align__(16) __nv_bfloat16 As[2][2][64][40];
    __shared__ __align__(16) __nv_bfloat16 Bs[2][2][64][40];
    __shared__ float s_red[4][64];
    __shared__ float s_inv[64];

    const int tid = threadIdx.x, lane = tid & 31, wid = tid >> 5;
    const int wm = wid & 1, wn = wid >> 1;

    float acc[2][2][4];
#pragma unroll
    for (int i = 0; i < 2; i++)
#pragma unroll
        for (int j = 0; j < 2; j++)
#pragma unroll
            for (int k = 0; k < 4; k++) acc[i][j][k] = 0.0f;

    const int nk = (K + 31) >> 5;
    load64(As[0], Ahi, Alo, m0, 1 << 30, K, 0, tid);
    load64(Bs[0], Bhi, Blo, n0, N, K, 0, tid);
    CP_COMMIT();

    int st = 0;
    for (int it = 0; it < nk; it++) {
        if (it + 1 < nk) {
            load64(As[st ^ 1], Ahi, Alo, m0, 1 << 30, K, (it + 1) * 32, tid);
            load64(Bs[st ^ 1], Bhi, Blo, n0, N, K, (it + 1) * 32, tid);
            CP_COMMIT();
            CP_WAIT1();
        } else {
            CP_WAIT0();
        }
        __syncthreads();

#pragma unroll
        for (int ks = 0; ks < 32; ks += 16) {
            uint32_t ah[2][4], al[2][4], bh[4], bl[4];
            int arow = wm * 32 + (lane & 15);
            int acol = ks + ((lane >> 4) << 3);
#pragma unroll
            for (int mi = 0; mi < 2; mi++) {
                ldsm4(ah[mi], (uint32_t)__cvta_generic_to_shared(&As[st][0][arow + mi * 16][acol]));
                ldsm4(al[mi], (uint32_t)__cvta_generic_to_shared(&As[st][1][arow + mi * 16][acol]));
            }
            int brow = wn * 16 + (lane & 7) + ((lane >> 4) << 3);
            int bcol = ks + (lane & 8);
            ldsm4(bh, (uint32_t)__cvta_generic_to_shared(&Bs[st][0][brow][bcol]));
            ldsm4(bl, (uint32_t)__cvta_generic_to_shared(&Bs[st][1][brow][bcol]));
#pragma unroll
            for (int mi = 0; mi < 2; mi++)
#pragma unroll
                for (int ni = 0; ni < 2; ni++) {
                    mma16816(acc[mi][ni], ah[mi], &bh[ni * 2]);
                    mma16816(acc[mi][ni], ah[mi], &bl[ni * 2]);
                    mma16816(acc[mi][ni], al[mi], &bh[ni * 2]);
                }
        }
        __syncthreads();
        st ^= 1;
    }

    const int g  = lane >> 2;
    const int tg = (lane & 3) << 1;

    if (MODE2 == 0) {
#pragma unroll
        for (int mi = 0; mi < 2; mi++)
#pragma unroll
            for (int ni = 0; ni < 2; ni++) {
                int col = n0 + wn * 16 + ni * 8 + tg;
                if (col >= N) continue;
#pragma unroll
                for (int hf = 0; hf < 2; hf++) {
                    int row = m0 + wm * 32 + mi * 16 + g + hf * 8;
                    Cf[(size_t)row * N + col]     = acc[mi][ni][hf * 2 + 0] + bias[col];
                    Cf[(size_t)row * N + col + 1] = acc[mi][ni][hf * 2 + 1] + bias[col + 1];
                }
            }
    } else {
        // Fused norm: add bias, reduce sum(v^2) per row, scale, split-store.
#pragma unroll
        for (int mi = 0; mi < 2; mi++)
#pragma unroll
            for (int hf = 0; hf < 2; hf++) {
                int rloc = wm * 32 + mi * 16 + hf * 8 + g;
                float ss = 0.0f;
#pragma unroll
                for (int ni = 0; ni < 2; ni++) {
                    int col = wn * 16 + ni * 8 + tg;
                    if (col < N) {
                        float v0 = acc[mi][ni][hf * 2 + 0] + bias[col];
                        float v1 = acc[mi][ni][hf * 2 + 1] + bias[col + 1];
                        acc[mi][ni][hf * 2 + 0] = v0;
                        acc[mi][ni][hf * 2 + 1] = v1;
                        ss += v0 * v0 + v1 * v1;
                    }
                }
                ss += __shfl_xor_sync(0xffffffffu, ss, 1);
                ss += __shfl_xor_sync(0xffffffffu, ss, 2);
                if ((lane & 3) == 0) s_red[wn][rloc] = ss;
            }
        __syncthreads();
        if (tid < 64) {
            float t = s_red[0][tid] + s_red[1][tid] + s_red[2][tid] + s_red[3][tid];
            s_inv[tid] = 1.0f / (sqrtf(t) + 1e-7f);
        }
        __syncthreads();
#pragma unroll
        for (int mi = 0; mi < 2; mi++)
#pragma unroll
            for (int hf = 0; hf < 2; hf++) {
                int rloc = wm * 32 + mi * 16 + hf * 8 + g;
                float inv = s_inv[rloc];
                int row = m0 + rloc;
#pragma unroll
                for (int ni = 0; ni < 2; ni++) {
                    int col = wn * 16 + ni * 8 + tg;
                    if (col >= N) continue;
                    float v0 = acc[mi][ni][hf * 2 + 0] * inv;
                    float v1 = acc[mi][ni][hf * 2 + 1] * inv;
                    __nv_bfloat16 h0, l0, h1, l1;
                    split_bf16(v0, h0, l0);
                    split_bf16(v1, h1, l1);
                    size_t o = (size_t)row * N + col;
                    Zhi[o] = h0; Zhi[o + 1] = h1;
                    Zlo[o] = l0; Zlo[o + 1] = l1;
                }
            }
    }
}

// ---------------------------------------------------------------------------
// GEMM1: hid = relu(ft @ w1^T + b1). Blocks/layer = C -> cum 64,192,448,960.
// ---------------------------------------------------------------------------
__global__ __launch_bounds__(256) void gemm1_all(InPtrs ip)
{
    int b = blockIdx.x;
    int l = (b < 64) ? 0 : (b < 192) ? 1 : (b < 448) ? 2 : 3;
    const int base[4] = {0, 64, 192, 448};
    int t = b - base[l];
    int C = 64 << l;
    int tilesX = C >> 6;
    int by = t / tilesX, bx = t % tilesX;
    size_t fo = (size_t)8192 * c_cumC[l];
    gemm128<1>(g_fthi + fo, g_ftlo + fo, g_whi + c_cumW[l], g_wlo + c_cumW[l],
               ip.b1[l], g_hidhi + fo, g_hidlo + fo, nullptr, nullptr, 0,
               by * 128, bx * 64, C, C);
}

// ---------------------------------------------------------------------------
// GEMM2: layers 0-2 fused norm (128 blocks each); layer 3 plain (256 blocks).
// cum: 128, 256, 384, 640.
// ---------------------------------------------------------------------------
__global__ __launch_bounds__(256) void gemm2_all(InPtrs ip)
{
    int b = blockIdx.x;
    if (b < 384) {
        int l = b >> 7;
        int m0 = (b & 127) * 64;
        int C = 64 << l, Co = 16 << l;
        size_t fo = (size_t)8192 * c_cumC[l];
        size_t zo = (size_t)8192 * c_cumZ[l];
        gemm64<1>(g_hidhi + fo, g_hidlo + fo,
                  g_whi + c_cumW[l] + C * C, g_wlo + c_cumW[l] + C * C,
                  ip.b2[l], nullptr, g_zhi + zo, g_zlo + zo,
                  m0, 0, Co, C);
    } else {
        int t = b - 384;                       // layer 3: Co=128, K=512
        int m0 = (t >> 1) * 64, n0 = (t & 1) * 64;
        size_t fo = (size_t)8192 * c_cumC[3];
        gemm64<0>(g_hidhi + fo, g_hidlo + fo,
                  g_whi + c_cumW[3] + 512 * 512, g_wlo + c_cumW[3] + 512 * 512,
                  ip.b2[3], g_zf, nullptr, nullptr,
                  m0, n0, 128, 512);
    }
}

// ---------------------------------------------------------------------------
// Layer-3 norm: 8192 rows of 128, one warp per row, float4 loads.
// ---------------------------------------------------------------------------
__global__ void norm3_kernel()
{
    int row = blockIdx.x * 8 + (threadIdx.x >> 5);
    int lane = threadIdx.x & 31;
    const float* r = g_zf + (size_t)row * 128;
    float4 q = __ldg((const float4*)r + lane);
    float ss = q.x * q.x + q.y * q.y + q.z * q.z + q.w * q.w;
#pragma unroll
    for (int o = 16; o; o >>= 1) ss += __shfl_xor_sync(0xffffffffu, ss, o);
    float inv = 1.0f / (sqrtf(ss) + 1e-7f);
    size_t zo = (size_t)8192 * 112 + (size_t)row * 128 + lane * 4;
    float v[4] = {q.x * inv, q.y * inv, q.z * inv, q.w * inv};
    __nv_bfloat16 h[4], lo[4];
#pragma unroll
    for (int i = 0; i < 4; i++) split_bf16(v[i], h[i], lo[i]);
    *(uint2*)(g_zhi + zo) = *(const uint2*)&h[0];
    *(uint2*)(g_zlo + zo) = *(const uint2*)&lo[0];
}

// ---------------------------------------------------------------------------
// Scores + fused exp-sum: 8 batch x 4 by x 8 bx = 256 blocks/layer -> 1024.
// ---------------------------------------------------------------------------
__global__ __launch_bounds__(256) void scores_all()
{
    int b = blockIdx.x;
    int l = b >> 8;
    int t = b & 255;
    int batch = t >> 5;
    t &= 31;
    int by = t >> 3, bx = t & 7;
    int Co = 16 << l;
    size_t zb = (size_t)8192 * c_cumZ[l];
    const __nv_bfloat16* qhi = g_zhi + zb + (size_t)batch * 512 * Co;
    const __nv_bfloat16* qlo = g_zlo + zb + (size_t)batch * 512 * Co;
    const __nv_bfloat16* khi = g_zhi + zb + (size_t)(4096 + batch * 512) * Co;
    const __nv_bfloat16* klo = g_zlo + zb + (size_t)(4096 + batch * 512) * Co;
    float* esum = g_esum + (size_t)(l * 8 + batch) * 512 * 8;
    float* diag = g_diag + (size_t)(l * 8 + batch) * 512;
    gemm128<3>(qhi, qlo, khi, klo, nullptr, nullptr, nullptr,
               esum, diag, bx, by * 128, bx * 64, 512, Co);
}

// ---------------------------------------------------------------------------
__global__ void lse_final()
{
    int row = blockIdx.x * 256 + threadIdx.x;
    float s = 0.0f;
#pragma unroll
    for (int i = 0; i < 8; i++) s += g_esum[(size_t)row * 8 + i];
    float loss = (1.0f - g_diag[row]) * INVTAU + logf(s);
    __shared__ float sh[256];
    sh[threadIdx.x] = loss;
    __syncthreads();
    for (int st = 128; st; st >>= 1) {
        if (threadIdx.x < st) sh[threadIdx.x] += sh[threadIdx.x + st];
        __syncthreads();
    }
    if (threadIdx.x == 0) g_partial[blockIdx.x] = sh[0];
}

__global__ void final_kernel(float* __restrict__ out)
{
    __shared__ float sh[64];
    if (threadIdx.x < 64) sh[threadIdx.x] = g_partial[threadIdx.x];
    __syncthreads();
    if (threadIdx.x == 0) {
        float s = 0.0f;
        for (int i = 0; i < 64; i++) s += sh[i];
        out[0] = s / 4096.0f;
    }
}

// ---------------------------------------------------------------------------
extern "C" void kernel_launch(void* const* d_in, const int* in_sizes, int n_in,
                              void* d_out, int out_size)
{
    (void)n_in; (void)out_size;
    bool dict_order = (in_sizes[0] == in_sizes[1]) && (in_sizes[2] == 128);

    InPtrs ip;
    for (int l = 0; l < 4; l++) {
        int ifq, ifk, isid, iw1, ib1, iw2, ib2;
        if (dict_order) {
            int base = 7 * l;
            ifq = base; ifk = base + 1; isid = base + 2;
            iw1 = base + 3; ib1 = base + 4; iw2 = base + 5; ib2 = base + 6;
        } else {
            ifq = l; ifk = 4 + l; isid = 8 + l;
            iw1 = 12 + l * 4; ib1 = iw1 + 1; iw2 = iw1 + 2; ib2 = iw1 + 3;
        }
        ip.fq[l]  = (const float*)d_in[ifq];
        ip.fk[l]  = (const float*)d_in[ifk];
        ip.sid[l] = (const int*)d_in[isid];
        ip.w1[l]  = (const float*)d_in[iw1];
        ip.b1[l]  = (const float*)d_in[ib1];
        ip.w2[l]  = (const float*)d_in[iw2];
        ip.b2[l]  = (const float*)d_in[ib2];
    }

    gw_all<<<2660, 256>>>(ip);
    gemm1_all<<<960, 256>>>(ip);
    gemm2_all<<<640, 256>>>(ip);
    norm3_kernel<<<1024, 256>>>();
    scores_all<<<1024, 256>>>();
    lse_final<<<64, 256>>>();
    final_kernel<<<1, 256>>>((float*)d_out);
}